// round 13
// baseline (speedup 1.0000x reference)
#include <cuda_runtime.h>
#include <cuda_bf16.h>
#include <math.h>

// Problem constants (fixed shapes)
#define SEQ   8
#define BB    8
#define CIN   16
#define HH    96
#define WW    96
#define HW    (HH*WW)      // 9216
#define NF    64
#define LL    5
#define C3    (3*NF)       // 192
#define CF    32           // f channels
#define CFL   (2*LL)       // 10 flow channels
#define KW    (LL*NF)      // 320 warped channels

// -------------------- scratch (device globals; no allocation) --------------------
__device__ float g_i2h  [(size_t)SEQ * BB * C3 * HW];
__device__ float g_f    [(size_t)BB * CF  * HW];
__device__ float g_flows[(size_t)BB * CFL * HW];

// fast transcendentals (accuracy budget is 1e-3; these are ~1e-7 level here)
__device__ __forceinline__ float fsigmoid(float x) {
    return 1.f / (1.f + __expf(-x));
}
__device__ __forceinline__ float ftanh(float x) {
    float e = __expf(2.f * x);
    return (e - 1.f) / (e + 1.f);
}

// -------------------- utility --------------------
__global__ void copy_kernel(const float* __restrict__ src, float* __restrict__ dst, int n) {
    int i = blockIdx.x * blockDim.x + threadIdx.x;
    if (i < n) dst[i] = src[i];
}

// ==================== conv3: i2h for ALL timesteps ====================
// 16 oc/block, 2x2 px/thread, 32x32 tile, double-buffered staging.
// grid (9, 12, SEQ*BB), block (16,16)
__global__ void __launch_bounds__(256, 2)
conv3_kernel(const float* __restrict__ x, const float* __restrict__ w,
             const float* __restrict__ bias)
{
    __shared__ __align__(16) float sm[2][34 * 34];
    __shared__ __align__(16) float sw[CIN * 16 * 12];   // [ic][o][12], pad 9->12

    int sb  = blockIdx.z;
    int ocg = blockIdx.y;
    int tileY = (blockIdx.x / 3) * 32;
    int tileX = (blockIdx.x % 3) * 32;
    int tid = threadIdx.y * 16 + threadIdx.x;

    for (int i = tid; i < CIN * 16 * 12; i += 256) {
        int ic = i / 192, rem = i % 192;
        int o = rem / 12, k = rem % 12;
        sw[i] = (k < 9) ? w[((ocg * 16 + o) * CIN + ic) * 9 + k] : 0.f;
    }

    const float* xb = x + (size_t)sb * CIN * HW;

    float rbuf[5];
#define C3_LD(IC) { \
        const float* src = xb + (size_t)(IC) * HW; \
        _Pragma("unroll") \
        for (int k = 0; k < 5; k++) { \
            int i = tid + k * 256; float v = 0.f; \
            if (i < 34 * 34) { \
                int r = i / 34, c = i % 34; \
                int gy = tileY + r - 1, gx = tileX + c - 1; \
                if ((unsigned)gy < (unsigned)HH && (unsigned)gx < (unsigned)WW) \
                    v = src[gy * WW + gx]; \
            } \
            rbuf[k] = v; \
        } }
#define C3_ST(BUF) { \
        _Pragma("unroll") \
        for (int k = 0; k < 5; k++) { \
            int i = tid + k * 256; \
            if (i < 34 * 34) sm[BUF][i] = rbuf[k]; \
        } }

    float acc[16][4];
#pragma unroll
    for (int o = 0; o < 16; o++)
#pragma unroll
        for (int p = 0; p < 4; p++) acc[o][p] = 0.f;

    C3_LD(0);
    int buf = 0;
    for (int ic = 0; ic < CIN; ic++) {
        C3_ST(buf);
        __syncthreads();
        if (ic + 1 < CIN) C3_LD(ic + 1);

        int ry = threadIdx.y * 2, rx = threadIdx.x * 2;
        float win[4][4];
#pragma unroll
        for (int i = 0; i < 4; i++) {
            float2 a = *(const float2*)&sm[buf][(ry + i) * 34 + rx];
            float2 bq = *(const float2*)&sm[buf][(ry + i) * 34 + rx + 2];
            win[i][0] = a.x; win[i][1] = a.y; win[i][2] = bq.x; win[i][3] = bq.y;
        }

#pragma unroll
        for (int o = 0; o < 16; o++) {
            float wv[12];
#pragma unroll
            for (int q = 0; q < 3; q++)
                *(float4*)&wv[q * 4] = *(const float4*)&sw[(ic * 16 + o) * 12 + q * 4];
#pragma unroll
            for (int py = 0; py < 2; py++)
#pragma unroll
                for (int px = 0; px < 2; px++) {
                    acc[o][py*2+px] +=
                        win[py  ][px]*wv[0] + win[py  ][px+1]*wv[1] + win[py  ][px+2]*wv[2]
                      + win[py+1][px]*wv[3] + win[py+1][px+1]*wv[4] + win[py+1][px+2]*wv[5]
                      + win[py+2][px]*wv[6] + win[py+2][px+1]*wv[7] + win[py+2][px+2]*wv[8];
                }
        }
        buf ^= 1;
    }
#undef C3_LD
#undef C3_ST

    int oy = tileY + threadIdx.y * 2, ox = tileX + threadIdx.x * 2;
#pragma unroll
    for (int o = 0; o < 16; o++) {
        float bv = bias[ocg * 16 + o];
        float* yp = g_i2h + ((size_t)sb * C3 + ocg * 16 + o) * HW;
        yp[oy * WW + ox]           = acc[o][0] + bv;
        yp[oy * WW + ox + 1]       = acc[o][1] + bv;
        yp[(oy + 1) * WW + ox]     = acc[o][2] + bv;
        yp[(oy + 1) * WW + ox + 1] = acc[o][3] + bv;
    }
}

// ==================== fused f conv: tanh(conv5(x) + conv5(h_prev)) ====================
// 8 oc/block, 2x2 px/thread, double-buffered; window LDS.64, weights padded 25->28.
// grid (9, 4, BB), block (16,16)
__global__ void __launch_bounds__(256, 2)
conv5_f_kernel(const float* __restrict__ x, const float* __restrict__ hp,
               const float* __restrict__ i2f_w, const float* __restrict__ h2f_w,
               const float* __restrict__ i2f_b, const float* __restrict__ h2f_b,
               int skip_h)
{
    __shared__ __align__(16) float sm[2][36 * 36];
    __shared__ __align__(16) float sw[2][8 * 28];

    int b   = blockIdx.z;
    int ocg = blockIdx.y;
    int tileY = (blockIdx.x / 3) * 32;
    int tileX = (blockIdx.x % 3) * 32;
    int tid = threadIdx.y * 16 + threadIdx.x;

    float acc[8][4];
#pragma unroll
    for (int o = 0; o < 8; o++)
#pragma unroll
        for (int p = 0; p < 4; p++) acc[o][p] = 0.f;

    int ctot = skip_h ? CIN : (CIN + NF);

    float rbuf[6], wreg = 0.f;
#define F_LD(IC) { \
        const float* src; const float* wsrc; int cnum, icl; \
        if ((IC) < CIN) { src = x + ((size_t)b * CIN + (IC)) * HW; wsrc = i2f_w; cnum = CIN; icl = (IC); } \
        else { src = hp + ((size_t)b * NF + ((IC) - CIN)) * HW; wsrc = h2f_w; cnum = NF; icl = (IC) - CIN; } \
        _Pragma("unroll") \
        for (int k = 0; k < 6; k++) { \
            int i = tid + k * 256; float v = 0.f; \
            if (i < 36 * 36) { \
                int r = i / 36, c = i % 36; \
                int gy = tileY + r - 2, gx = tileX + c - 2; \
                if ((unsigned)gy < (unsigned)HH && (unsigned)gx < (unsigned)WW) \
                    v = src[gy * WW + gx]; \
            } \
            rbuf[k] = v; \
        } \
        if (tid < 224) { \
            int o = tid / 28, kk = tid % 28; \
            wreg = (kk < 25) ? wsrc[((size_t)(ocg * 8 + o) * cnum + icl) * 25 + kk] : 0.f; \
        } }
#define F_ST(BUF) { \
        _Pragma("unroll") \
        for (int k = 0; k < 6; k++) { \
            int i = tid + k * 256; \
            if (i < 36 * 36) sm[BUF][i] = rbuf[k]; \
        } \
        if (tid < 224) sw[BUF][tid] = wreg; }

    F_LD(0);
    int buf = 0;
    for (int ic = 0; ic < ctot; ic++) {
        F_ST(buf);
        __syncthreads();
        if (ic + 1 < ctot) F_LD(ic + 1);

        int ry = threadIdx.y * 2, rx = threadIdx.x * 2;
        float win[6][6];
#pragma unroll
        for (int i = 0; i < 6; i++) {
            float2 a = *(const float2*)&sm[buf][(ry + i) * 36 + rx];
            float2 bq = *(const float2*)&sm[buf][(ry + i) * 36 + rx + 2];
            float2 cq = *(const float2*)&sm[buf][(ry + i) * 36 + rx + 4];
            win[i][0] = a.x;  win[i][1] = a.y;
            win[i][2] = bq.x; win[i][3] = bq.y;
            win[i][4] = cq.x; win[i][5] = cq.y;
        }

#pragma unroll
        for (int o = 0; o < 8; o++) {
            float wv[28];
#pragma unroll
            for (int q = 0; q < 7; q++)
                *(float4*)&wv[q * 4] = *(const float4*)&sw[buf][o * 28 + q * 4];
#pragma unroll
            for (int ky = 0; ky < 5; ky++)
#pragma unroll
                for (int kx = 0; kx < 5; kx++) {
                    float wvv = wv[ky * 5 + kx];
                    acc[o][0] += win[ky  ][kx  ] * wvv;
                    acc[o][1] += win[ky  ][kx+1] * wvv;
                    acc[o][2] += win[ky+1][kx  ] * wvv;
                    acc[o][3] += win[ky+1][kx+1] * wvv;
                }
        }
        buf ^= 1;
    }
#undef F_LD
#undef F_ST

    int oy = tileY + threadIdx.y * 2, ox = tileX + threadIdx.x * 2;
#pragma unroll
    for (int o = 0; o < 8; o++) {
        int oc = ocg * 8 + o;
        float bv = i2f_b[oc] + h2f_b[oc];
        float* yp = g_f + ((size_t)b * CF + oc) * HW;
        yp[oy * WW + ox]           = ftanh(acc[o][0] + bv);
        yp[oy * WW + ox + 1]       = ftanh(acc[o][1] + bv);
        yp[(oy + 1) * WW + ox]     = ftanh(acc[o][2] + bv);
        yp[(oy + 1) * WW + ox + 1] = ftanh(acc[o][3] + bv);
    }
}

// ==================== flows conv: conv5(g_f) -> g_flows ====================
// all 10 oc, 2x2 px/thread; all weights preloaded padded.
// grid (9, 1, BB), block (16,16)
__global__ void __launch_bounds__(256, 2)
conv5_flows_kernel(const float* __restrict__ flows_w, const float* __restrict__ flows_b)
{
    __shared__ __align__(16) float sm[2][36 * 36];
    __shared__ __align__(16) float sw[CFL * CF * 28];

    int b = blockIdx.z;
    int tileY = (blockIdx.x / 3) * 32;
    int tileX = (blockIdx.x % 3) * 32;
    int tid = threadIdx.y * 16 + threadIdx.x;

    for (int i = tid; i < CFL * CF * 28; i += 256) {
        int k = i % 28;
        int oc_ic = i / 28;
        sw[i] = (k < 25) ? flows_w[oc_ic * 25 + k] : 0.f;
    }

    float acc[CFL][4];
#pragma unroll
    for (int o = 0; o < CFL; o++)
#pragma unroll
        for (int p = 0; p < 4; p++) acc[o][p] = 0.f;

    float rbuf[6];
#define FL_LD(IC) { \
        const float* src = g_f + ((size_t)b * CF + (IC)) * HW; \
        _Pragma("unroll") \
        for (int k = 0; k < 6; k++) { \
            int i = tid + k * 256; float v = 0.f; \
            if (i < 36 * 36) { \
                int r = i / 36, c = i % 36; \
                int gy = tileY + r - 2, gx = tileX + c - 2; \
                if ((unsigned)gy < (unsigned)HH && (unsigned)gx < (unsigned)WW) \
                    v = src[gy * WW + gx]; \
            } \
            rbuf[k] = v; \
        } }
#define FL_ST(BUF) { \
        _Pragma("unroll") \
        for (int k = 0; k < 6; k++) { \
            int i = tid + k * 256; \
            if (i < 36 * 36) sm[BUF][i] = rbuf[k]; \
        } }

    FL_LD(0);
    int buf = 0;
    for (int ic = 0; ic < CF; ic++) {
        FL_ST(buf);
        __syncthreads();
        if (ic + 1 < CF) FL_LD(ic + 1);

        int ry = threadIdx.y * 2, rx = threadIdx.x * 2;
        float win[6][6];
#pragma unroll
        for (int i = 0; i < 6; i++) {
            float2 a = *(const float2*)&sm[buf][(ry + i) * 36 + rx];
            float2 bq = *(const float2*)&sm[buf][(ry + i) * 36 + rx + 2];
            float2 cq = *(const float2*)&sm[buf][(ry + i) * 36 + rx + 4];
            win[i][0] = a.x;  win[i][1] = a.y;
            win[i][2] = bq.x; win[i][3] = bq.y;
            win[i][4] = cq.x; win[i][5] = cq.y;
        }

#pragma unroll
        for (int o = 0; o < CFL; o++) {
            float wv[28];
#pragma unroll
            for (int q = 0; q < 7; q++)
                *(float4*)&wv[q * 4] = *(const float4*)&sw[(o * CF + ic) * 28 + q * 4];
#pragma unroll
            for (int ky = 0; ky < 5; ky++)
#pragma unroll
                for (int kx = 0; kx < 5; kx++) {
                    float wvv = wv[ky * 5 + kx];
                    acc[o][0] += win[ky  ][kx  ] * wvv;
                    acc[o][1] += win[ky  ][kx+1] * wvv;
                    acc[o][2] += win[ky+1][kx  ] * wvv;
                    acc[o][3] += win[ky+1][kx+1] * wvv;
                }
        }
        buf ^= 1;
    }
#undef FL_LD
#undef FL_ST

    int oy = tileY + threadIdx.y * 2, ox = tileX + threadIdx.x * 2;
#pragma unroll
    for (int o = 0; o < CFL; o++) {
        float bv = flows_b[o];
        float* yp = g_flows + ((size_t)b * CFL + o) * HW;
        yp[oy * WW + ox]           = acc[o][0] + bv;
        yp[oy * WW + ox + 1]       = acc[o][1] + bv;
        yp[(oy + 1) * WW + ox]     = acc[o][2] + bv;
        yp[(oy + 1) * WW + ox + 1] = acc[o][3] + bv;
    }
}

// ==================== fused warp + GEMM + gates ====================
// A values (warped h_prev) are computed on the fly during A-staging from
// L2-resident h_prev + precomputed per-(l,px) taps; the 94MB/step g_warp
// intermediate never exists. BM=192, BN=64, BK=16 (each k-tile within one l).
// Epilogue applies GRU gates. grid (144, BB), block 256.
__global__ void __launch_bounds__(256, 2)
warp_gemm_gates_kernel(const float* __restrict__ Wm, const float* __restrict__ bias,
                       int t, const float* __restrict__ hp, float* __restrict__ hn)
{
    const int K = KW, N = HW;
    __shared__ __align__(16) float Ws[2][16][192];   // 24 KB
    __shared__ __align__(16) float As[2][16][64];    //  8 KB
    __shared__ __align__(16) int4   s_off[LL][64];   //  5 KB
    __shared__ __align__(16) float4 s_wt [LL][64];   //  5 KB

    int b  = blockIdx.y;
    int n0 = blockIdx.x * 64;
    int tid = threadIdx.x;
    int tx = tid % 16;        // pixel group: 4 px
    int ty = tid / 16;        // channel group: c0 = ty*4

    // ---- precompute bilinear taps for this block's 64 pixels x 5 levels ----
    for (int i = tid; i < LL * 64; i += 256) {
        int l = i / 64, p = i % 64;
        int pix = n0 + p;
        int gx = pix % WW;
        int gy = pix / WW;

        const float* fl = g_flows + ((size_t)b * CFL + 2 * l) * HW;
        float fx = fl[pix];
        float fy = fl[HW + pix];

        float vx = (float)gx - fx;
        float vy = (float)gy - fy;
        float gxn = 2.f * vx / (float)(WW - 1) - 1.f;
        float gyn = 2.f * vy / (float)(HH - 1) - 1.f;
        float sx = ((gxn + 1.f) * (float)WW - 1.f) * 0.5f;
        float sy = ((gyn + 1.f) * (float)HH - 1.f) * 0.5f;

        float x0f = floorf(sx), y0f = floorf(sy);
        int x0 = (int)x0f, y0 = (int)y0f;
        int x1 = x0 + 1, y1 = y0 + 1;
        float wx1 = sx - x0f, wx0 = 1.f - wx1;
        float wy1 = sy - y0f, wy0 = 1.f - wy1;

        bool vx0 = (x0 >= 0) && (x0 < WW);
        bool vx1 = (x1 >= 0) && (x1 < WW);
        bool vy0 = (y0 >= 0) && (y0 < HH);
        bool vy1 = (y1 >= 0) && (y1 < HH);

        int xc0 = min(max(x0, 0), WW - 1);
        int xc1 = min(max(x1, 0), WW - 1);
        int yc0 = min(max(y0, 0), HH - 1);
        int yc1 = min(max(y1, 0), HH - 1);

        float4 wt;
        wt.x = (vy0 && vx0) ? wy0 * wx0 : 0.f;
        wt.y = (vy0 && vx1) ? wy0 * wx1 : 0.f;
        wt.z = (vy1 && vx0) ? wy1 * wx0 : 0.f;
        wt.w = (vy1 && vx1) ? wy1 * wx1 : 0.f;

        int4 off;
        off.x = yc0 * WW + xc0;
        off.y = yc0 * WW + xc1;
        off.z = yc1 * WW + xc0;
        off.w = yc1 * WW + xc1;

        s_off[l][p] = off;
        s_wt[l][p]  = wt;
    }
    __syncthreads();

    const float* hpb = hp + (size_t)b * NF * HW;

    float acc[3][4][4];       // [component][c][px]
#pragma unroll
    for (int g = 0; g < 3; g++)
#pragma unroll
        for (int i = 0; i < 4; i++)
#pragma unroll
            for (int j = 0; j < 4; j++) acc[g][i][j] = 0.f;

    int arow = tid / 16;      // k-row within tile
    int acol = (tid % 16) * 4;

    float pa[4];
    float pw[12];

#define GG_LD(K0) { \
        int l = (K0) / 64; \
        int c = ((K0) & 63) + arow; \
        const float* hc = hpb + (size_t)c * HW; \
        _Pragma("unroll") \
        for (int j = 0; j < 4; j++) { \
            int p = acol + j; \
            int4   o4 = s_off[l][p]; \
            float4 w4 = s_wt[l][p]; \
            pa[j] = w4.x * __ldg(hc + o4.x) + w4.y * __ldg(hc + o4.y) \
                  + w4.z * __ldg(hc + o4.z) + w4.w * __ldg(hc + o4.w); \
        } \
        _Pragma("unroll") \
        for (int r = 0; r < 12; r++) { \
            int i = tid + r * 256; \
            int m = i >> 4, kk = i & 15; \
            pw[r] = Wm[(size_t)m * K + (K0) + kk]; \
        } }
#define GG_ST(BUF) { \
        As[BUF][arow][acol]     = pa[0]; \
        As[BUF][arow][acol + 1] = pa[1]; \
        As[BUF][arow][acol + 2] = pa[2]; \
        As[BUF][arow][acol + 3] = pa[3]; \
        _Pragma("unroll") \
        for (int r = 0; r < 12; r++) { \
            int i = tid + r * 256; \
            int m = i >> 4, kk = i & 15; \
            Ws[BUF][kk][m] = pw[r]; \
        } }

    GG_LD(0);
    int buf = 0;
    for (int k0 = 0; k0 < K; k0 += 16) {
        GG_ST(buf);
        __syncthreads();
        if (k0 + 16 < K) GG_LD(k0 + 16);

#pragma unroll
        for (int kk = 0; kk < 16; kk++) {
            float4 a4 = *(const float4*)&As[buf][kk][tx * 4];
            float4 wr = *(const float4*)&Ws[buf][kk][ty * 4];
            float4 wu = *(const float4*)&Ws[buf][kk][ty * 4 + 64];
            float4 wm = *(const float4*)&Ws[buf][kk][ty * 4 + 128];
#define MM(G, WV) { \
            acc[G][0][0] += WV.x*a4.x; acc[G][0][1] += WV.x*a4.y; acc[G][0][2] += WV.x*a4.z; acc[G][0][3] += WV.x*a4.w; \
            acc[G][1][0] += WV.y*a4.x; acc[G][1][1] += WV.y*a4.y; acc[G][1][2] += WV.y*a4.z; acc[G][1][3] += WV.y*a4.w; \
            acc[G][2][0] += WV.z*a4.x; acc[G][2][1] += WV.z*a4.y; acc[G][2][2] += WV.z*a4.z; acc[G][2][3] += WV.z*a4.w; \
            acc[G][3][0] += WV.w*a4.x; acc[G][3][1] += WV.w*a4.y; acc[G][3][2] += WV.w*a4.z; acc[G][3][3] += WV.w*a4.w; }
            MM(0, wr) MM(1, wu) MM(2, wm)
#undef MM
        }
        buf ^= 1;
    }
#undef GG_LD
#undef GG_ST

    // epilogue: GRU gates for this thread's 4 channels x 4 pixels
    const float* i2h_t = g_i2h + (size_t)t * BB * C3 * HW;
    int np = n0 + tx * 4;

#pragma unroll
    for (int i = 0; i < 4; i++) {
        int c = ty * 4 + i;
        size_t base = ((size_t)b * C3 + c) * HW + np;
        float4 ir = *(const float4*)&i2h_t[base];
        float4 iu = *(const float4*)&i2h_t[base + (size_t)NF * HW];
        float4 im = *(const float4*)&i2h_t[base + (size_t)2 * NF * HW];
        float4 hp4 = *(const float4*)&hp[((size_t)b * NF + c) * HW + np];
        float br = bias[c], bu = bias[c + NF], bm = bias[c + 2 * NF];

        float4 outv;
#define GATE1(X, J) { \
        float r = fsigmoid(ir.X + acc[0][i][J] + br); \
        float u = fsigmoid(iu.X + acc[1][i][J] + bu); \
        float m = ftanh(im.X + r * (acc[2][i][J] + bm)); \
        outv.X = u * hp4.X + (1.f - u) * m; }
        GATE1(x, 0) GATE1(y, 1) GATE1(z, 2) GATE1(w, 3)
#undef GATE1

        *(float4*)&hn[((size_t)b * NF + c) * HW + np] = outv;
    }
}

// ==================== gates for t=0 only (h_prev = 0, h2h = bias) ====================
__global__ void gates_first_kernel(float* __restrict__ hn, const float* __restrict__ ret_b)
{
    int idx = blockIdx.x * blockDim.x + threadIdx.x;
    const int total4 = BB * NF * HW / 4;
    if (idx >= total4) return;

    int e = idx * 4;
    int pix = e % HW;
    int rest = e / HW;
    int c = rest % NF;
    int b = rest / NF;

    const float* i2h_t = g_i2h;   // t = 0
    size_t base = ((size_t)b * C3 + c) * HW + pix;
    float4 ir = *(const float4*)&i2h_t[base];
    float4 iu = *(const float4*)&i2h_t[base + (size_t)NF * HW];
    float4 im = *(const float4*)&i2h_t[base + (size_t)2 * NF * HW];

    float br = ret_b[c], bu = ret_b[c + NF], bm = ret_b[c + 2 * NF];

    float4 outv;
#define GATE1(X) { \
        float r = fsigmoid(ir.X + br); \
        float u = fsigmoid(iu.X + bu); \
        float m = ftanh(im.X + r * bm); \
        outv.X = (1.f - u) * m; }
    GATE1(x) GATE1(y) GATE1(z) GATE1(w)
#undef GATE1

    *(float4*)&hn[((size_t)b * NF + c) * HW + pix] = outv;
}

// -------------------- launcher --------------------
extern "C" void kernel_launch(void* const* d_in, const int* in_sizes, int n_in,
                              void* d_out, int out_size)
{
    const float* inputs  = (const float*)d_in[0];
    const float* i2h_w   = (const float*)d_in[1];
    const float* i2h_b   = (const float*)d_in[2];
    const float* i2f_w   = (const float*)d_in[3];
    const float* i2f_b   = (const float*)d_in[4];
    const float* h2f_w   = (const float*)d_in[5];
    const float* h2f_b   = (const float*)d_in[6];
    const float* flows_w = (const float*)d_in[7];
    const float* flows_b = (const float*)d_in[8];
    const float* ret_w   = (const float*)d_in[9];
    const float* ret_b   = (const float*)d_in[10];
    float* out = (float*)d_out;

    const int hstride = BB * NF * HW;
    const dim3 thr16(16, 16);

    conv3_kernel<<<dim3(9, C3 / 16, SEQ * BB), thr16>>>(inputs, i2h_w, i2h_b);

    for (int t = 0; t < SEQ; t++) {
        const float* x_t   = inputs + (size_t)t * BB * CIN * HW;
        const float* hprev = (t == 0) ? nullptr : out + (size_t)(t - 1) * hstride;
        float* hnew        = out + (size_t)t * hstride;
        int first = (t == 0) ? 1 : 0;

        conv5_f_kernel<<<dim3(9, CF / 8, BB), thr16>>>(x_t, hprev, i2f_w, h2f_w,
                                                       i2f_b, h2f_b, first);

        if (first) {
            gates_first_kernel<<<(hstride / 4 + 255) / 256, 256>>>(hnew, ret_b);
        } else {
            conv5_flows_kernel<<<dim3(9, 1, BB), thr16>>>(flows_w, flows_b);
            warp_gemm_gates_kernel<<<dim3(HW / 64, BB), 256>>>(ret_w, ret_b, t, hprev, hnew);
        }
    }

    if (out_size >= (SEQ + 1) * hstride) {
        copy_kernel<<<(hstride + 255) / 256, 256>>>(out + (size_t)(SEQ - 1) * hstride,
                                                    out + (size_t)SEQ * hstride, hstride);
    }
}

// round 14
// speedup vs baseline: 1.0914x; 1.0914x over previous
#include <cuda_runtime.h>
#include <cuda_bf16.h>
#include <math.h>

// Problem constants (fixed shapes)
#define SEQ   8
#define BB    8
#define CIN   16
#define HH    96
#define WW    96
#define HW    (HH*WW)      // 9216
#define NF    64
#define LL    5
#define C3    (3*NF)       // 192
#define CF    32           // f channels
#define CFL   (2*LL)       // 10 flow channels
#define KW    (LL*NF)      // 320 warped channels

// -------------------- scratch (device globals; no allocation) --------------------
__device__ float g_i2h  [(size_t)SEQ * BB * C3 * HW];
__device__ float g_f    [(size_t)BB * CF  * HW];
__device__ float g_flows[(size_t)BB * CFL * HW];

// fast transcendentals (accuracy budget is 1e-3; these are ~1e-7 level here)
__device__ __forceinline__ float fsigmoid(float x) {
    return 1.f / (1.f + __expf(-x));
}
__device__ __forceinline__ float ftanh(float x) {
    float e = __expf(2.f * x);
    return (e - 1.f) / (e + 1.f);
}

// -------------------- utility --------------------
__global__ void copy_kernel(const float* __restrict__ src, float* __restrict__ dst, int n) {
    int i = blockIdx.x * blockDim.x + threadIdx.x;
    if (i < n) dst[i] = src[i];
}

// ==================== conv3: i2h for ALL timesteps ====================
// 16 oc/block, 2x2 px/thread, 32x32 tile, double-buffered staging.
// grid (9, 12, SEQ*BB), block (16,16)
__global__ void __launch_bounds__(256, 2)
conv3_kernel(const float* __restrict__ x, const float* __restrict__ w,
             const float* __restrict__ bias)
{
    __shared__ __align__(16) float sm[2][34 * 34];
    __shared__ __align__(16) float sw[CIN * 16 * 12];   // [ic][o][12], pad 9->12

    int sb  = blockIdx.z;
    int ocg = blockIdx.y;
    int tileY = (blockIdx.x / 3) * 32;
    int tileX = (blockIdx.x % 3) * 32;
    int tid = threadIdx.y * 16 + threadIdx.x;

    for (int i = tid; i < CIN * 16 * 12; i += 256) {
        int ic = i / 192, rem = i % 192;
        int o = rem / 12, k = rem % 12;
        sw[i] = (k < 9) ? w[((ocg * 16 + o) * CIN + ic) * 9 + k] : 0.f;
    }

    const float* xb = x + (size_t)sb * CIN * HW;

    float rbuf[5];
#define C3_LD(IC) { \
        const float* src = xb + (size_t)(IC) * HW; \
        _Pragma("unroll") \
        for (int k = 0; k < 5; k++) { \
            int i = tid + k * 256; float v = 0.f; \
            if (i < 34 * 34) { \
                int r = i / 34, c = i % 34; \
                int gy = tileY + r - 1, gx = tileX + c - 1; \
                if ((unsigned)gy < (unsigned)HH && (unsigned)gx < (unsigned)WW) \
                    v = src[gy * WW + gx]; \
            } \
            rbuf[k] = v; \
        } }
#define C3_ST(BUF) { \
        _Pragma("unroll") \
        for (int k = 0; k < 5; k++) { \
            int i = tid + k * 256; \
            if (i < 34 * 34) sm[BUF][i] = rbuf[k]; \
        } }

    float acc[16][4];
#pragma unroll
    for (int o = 0; o < 16; o++)
#pragma unroll
        for (int p = 0; p < 4; p++) acc[o][p] = 0.f;

    C3_LD(0);
    int buf = 0;
    for (int ic = 0; ic < CIN; ic++) {
        C3_ST(buf);
        __syncthreads();
        if (ic + 1 < CIN) C3_LD(ic + 1);

        int ry = threadIdx.y * 2, rx = threadIdx.x * 2;
        float win[4][4];
#pragma unroll
        for (int i = 0; i < 4; i++) {
            float2 a = *(const float2*)&sm[buf][(ry + i) * 34 + rx];
            float2 bq = *(const float2*)&sm[buf][(ry + i) * 34 + rx + 2];
            win[i][0] = a.x; win[i][1] = a.y; win[i][2] = bq.x; win[i][3] = bq.y;
        }

#pragma unroll
        for (int o = 0; o < 16; o++) {
            float wv[12];
#pragma unroll
            for (int q = 0; q < 3; q++)
                *(float4*)&wv[q * 4] = *(const float4*)&sw[(ic * 16 + o) * 12 + q * 4];
#pragma unroll
            for (int py = 0; py < 2; py++)
#pragma unroll
                for (int px = 0; px < 2; px++) {
                    acc[o][py*2+px] +=
                        win[py  ][px]*wv[0] + win[py  ][px+1]*wv[1] + win[py  ][px+2]*wv[2]
                      + win[py+1][px]*wv[3] + win[py+1][px+1]*wv[4] + win[py+1][px+2]*wv[5]
                      + win[py+2][px]*wv[6] + win[py+2][px+1]*wv[7] + win[py+2][px+2]*wv[8];
                }
        }
        buf ^= 1;
    }
#undef C3_LD
#undef C3_ST

    int oy = tileY + threadIdx.y * 2, ox = tileX + threadIdx.x * 2;
#pragma unroll
    for (int o = 0; o < 16; o++) {
        float bv = bias[ocg * 16 + o];
        float* yp = g_i2h + ((size_t)sb * C3 + ocg * 16 + o) * HW;
        yp[oy * WW + ox]           = acc[o][0] + bv;
        yp[oy * WW + ox + 1]       = acc[o][1] + bv;
        yp[(oy + 1) * WW + ox]     = acc[o][2] + bv;
        yp[(oy + 1) * WW + ox + 1] = acc[o][3] + bv;
    }
}

// ==================== fused f conv: tanh(conv5(x) + conv5(h_prev)) ====================
// 8 oc/block, 2x2 px/thread, double-buffered; window LDS.64, weights padded 25->28.
// grid (9, 4, BB), block (16,16)
__global__ void __launch_bounds__(256, 2)
conv5_f_kernel(const float* __restrict__ x, const float* __restrict__ hp,
               const float* __restrict__ i2f_w, const float* __restrict__ h2f_w,
               const float* __restrict__ i2f_b, const float* __restrict__ h2f_b,
               int skip_h)
{
    __shared__ __align__(16) float sm[2][36 * 36];
    __shared__ __align__(16) float sw[2][8 * 28];

    int b   = blockIdx.z;
    int ocg = blockIdx.y;
    int tileY = (blockIdx.x / 3) * 32;
    int tileX = (blockIdx.x % 3) * 32;
    int tid = threadIdx.y * 16 + threadIdx.x;

    float acc[8][4];
#pragma unroll
    for (int o = 0; o < 8; o++)
#pragma unroll
        for (int p = 0; p < 4; p++) acc[o][p] = 0.f;

    int ctot = skip_h ? CIN : (CIN + NF);

    float rbuf[6], wreg = 0.f;
#define F_LD(IC) { \
        const float* src; const float* wsrc; int cnum, icl; \
        if ((IC) < CIN) { src = x + ((size_t)b * CIN + (IC)) * HW; wsrc = i2f_w; cnum = CIN; icl = (IC); } \
        else { src = hp + ((size_t)b * NF + ((IC) - CIN)) * HW; wsrc = h2f_w; cnum = NF; icl = (IC) - CIN; } \
        _Pragma("unroll") \
        for (int k = 0; k < 6; k++) { \
            int i = tid + k * 256; float v = 0.f; \
            if (i < 36 * 36) { \
                int r = i / 36, c = i % 36; \
                int gy = tileY + r - 2, gx = tileX + c - 2; \
                if ((unsigned)gy < (unsigned)HH && (unsigned)gx < (unsigned)WW) \
                    v = src[gy * WW + gx]; \
            } \
            rbuf[k] = v; \
        } \
        if (tid < 224) { \
            int o = tid / 28, kk = tid % 28; \
            wreg = (kk < 25) ? wsrc[((size_t)(ocg * 8 + o) * cnum + icl) * 25 + kk] : 0.f; \
        } }
#define F_ST(BUF) { \
        _Pragma("unroll") \
        for (int k = 0; k < 6; k++) { \
            int i = tid + k * 256; \
            if (i < 36 * 36) sm[BUF][i] = rbuf[k]; \
        } \
        if (tid < 224) sw[BUF][tid] = wreg; }

    F_LD(0);
    int buf = 0;
    for (int ic = 0; ic < ctot; ic++) {
        F_ST(buf);
        __syncthreads();
        if (ic + 1 < ctot) F_LD(ic + 1);

        int ry = threadIdx.y * 2, rx = threadIdx.x * 2;
        float win[6][6];
#pragma unroll
        for (int i = 0; i < 6; i++) {
            float2 a = *(const float2*)&sm[buf][(ry + i) * 36 + rx];
            float2 bq = *(const float2*)&sm[buf][(ry + i) * 36 + rx + 2];
            float2 cq = *(const float2*)&sm[buf][(ry + i) * 36 + rx + 4];
            win[i][0] = a.x;  win[i][1] = a.y;
            win[i][2] = bq.x; win[i][3] = bq.y;
            win[i][4] = cq.x; win[i][5] = cq.y;
        }

#pragma unroll
        for (int o = 0; o < 8; o++) {
            float wv[28];
#pragma unroll
            for (int q = 0; q < 7; q++)
                *(float4*)&wv[q * 4] = *(const float4*)&sw[buf][o * 28 + q * 4];
#pragma unroll
            for (int ky = 0; ky < 5; ky++)
#pragma unroll
                for (int kx = 0; kx < 5; kx++) {
                    float wvv = wv[ky * 5 + kx];
                    acc[o][0] += win[ky  ][kx  ] * wvv;
                    acc[o][1] += win[ky  ][kx+1] * wvv;
                    acc[o][2] += win[ky+1][kx  ] * wvv;
                    acc[o][3] += win[ky+1][kx+1] * wvv;
                }
        }
        buf ^= 1;
    }
#undef F_LD
#undef F_ST

    int oy = tileY + threadIdx.y * 2, ox = tileX + threadIdx.x * 2;
#pragma unroll
    for (int o = 0; o < 8; o++) {
        int oc = ocg * 8 + o;
        float bv = i2f_b[oc] + h2f_b[oc];
        float* yp = g_f + ((size_t)b * CF + oc) * HW;
        yp[oy * WW + ox]           = ftanh(acc[o][0] + bv);
        yp[oy * WW + ox + 1]       = ftanh(acc[o][1] + bv);
        yp[(oy + 1) * WW + ox]     = ftanh(acc[o][2] + bv);
        yp[(oy + 1) * WW + ox + 1] = ftanh(acc[o][3] + bv);
    }
}

// ==================== flows conv: conv5(g_f) -> g_flows ====================
// all 10 oc, 2x2 px/thread; all weights preloaded padded.
// grid (9, 1, BB), block (16,16)
__global__ void __launch_bounds__(256, 2)
conv5_flows_kernel(const float* __restrict__ flows_w, const float* __restrict__ flows_b)
{
    __shared__ __align__(16) float sm[2][36 * 36];
    __shared__ __align__(16) float sw[CFL * CF * 28];

    int b = blockIdx.z;
    int tileY = (blockIdx.x / 3) * 32;
    int tileX = (blockIdx.x % 3) * 32;
    int tid = threadIdx.y * 16 + threadIdx.x;

    for (int i = tid; i < CFL * CF * 28; i += 256) {
        int k = i % 28;
        int oc_ic = i / 28;
        sw[i] = (k < 25) ? flows_w[oc_ic * 25 + k] : 0.f;
    }

    float acc[CFL][4];
#pragma unroll
    for (int o = 0; o < CFL; o++)
#pragma unroll
        for (int p = 0; p < 4; p++) acc[o][p] = 0.f;

    float rbuf[6];
#define FL_LD(IC) { \
        const float* src = g_f + ((size_t)b * CF + (IC)) * HW; \
        _Pragma("unroll") \
        for (int k = 0; k < 6; k++) { \
            int i = tid + k * 256; float v = 0.f; \
            if (i < 36 * 36) { \
                int r = i / 36, c = i % 36; \
                int gy = tileY + r - 2, gx = tileX + c - 2; \
                if ((unsigned)gy < (unsigned)HH && (unsigned)gx < (unsigned)WW) \
                    v = src[gy * WW + gx]; \
            } \
            rbuf[k] = v; \
        } }
#define FL_ST(BUF) { \
        _Pragma("unroll") \
        for (int k = 0; k < 6; k++) { \
            int i = tid + k * 256; \
            if (i < 36 * 36) sm[BUF][i] = rbuf[k]; \
        } }

    FL_LD(0);
    int buf = 0;
    for (int ic = 0; ic < CF; ic++) {
        FL_ST(buf);
        __syncthreads();
        if (ic + 1 < CF) FL_LD(ic + 1);

        int ry = threadIdx.y * 2, rx = threadIdx.x * 2;
        float win[6][6];
#pragma unroll
        for (int i = 0; i < 6; i++) {
            float2 a = *(const float2*)&sm[buf][(ry + i) * 36 + rx];
            float2 bq = *(const float2*)&sm[buf][(ry + i) * 36 + rx + 2];
            float2 cq = *(const float2*)&sm[buf][(ry + i) * 36 + rx + 4];
            win[i][0] = a.x;  win[i][1] = a.y;
            win[i][2] = bq.x; win[i][3] = bq.y;
            win[i][4] = cq.x; win[i][5] = cq.y;
        }

#pragma unroll
        for (int o = 0; o < CFL; o++) {
            float wv[28];
#pragma unroll
            for (int q = 0; q < 7; q++)
                *(float4*)&wv[q * 4] = *(const float4*)&sw[(o * CF + ic) * 28 + q * 4];
#pragma unroll
            for (int ky = 0; ky < 5; ky++)
#pragma unroll
                for (int kx = 0; kx < 5; kx++) {
                    float wvv = wv[ky * 5 + kx];
                    acc[o][0] += win[ky  ][kx  ] * wvv;
                    acc[o][1] += win[ky  ][kx+1] * wvv;
                    acc[o][2] += win[ky+1][kx  ] * wvv;
                    acc[o][3] += win[ky+1][kx+1] * wvv;
                }
        }
        buf ^= 1;
    }
#undef FL_LD
#undef FL_ST

    int oy = tileY + threadIdx.y * 2, ox = tileX + threadIdx.x * 2;
#pragma unroll
    for (int o = 0; o < CFL; o++) {
        float bv = flows_b[o];
        float* yp = g_flows + ((size_t)b * CFL + o) * HW;
        yp[oy * WW + ox]           = acc[o][0] + bv;
        yp[oy * WW + ox + 1]       = acc[o][1] + bv;
        yp[(oy + 1) * WW + ox]     = acc[o][2] + bv;
        yp[(oy + 1) * WW + ox + 1] = acc[o][3] + bv;
    }
}

// ==================== fused warp + GEMM + gates (v2: no spills) ====================
// Single-buffer, two-sync staging: gathered-A and W go straight to smem, so
// staging temporaries die before the MMA loop (live set = 48 accs + loop state).
// Ws/As rows padded (196/68 floats) to kill the 16-way STS bank conflicts of the
// unpadded layouts. BM=192, BN=64, BK=16; grid (144, BB), block 256.
__global__ void __launch_bounds__(256, 2)
warp_gemm_gates_kernel(const float* __restrict__ Wm, const float* __restrict__ bias,
                       int t, const float* __restrict__ hp, float* __restrict__ hn)
{
    const int K = KW, N = HW;
    __shared__ __align__(16) float Ws[16][196];      // 12.25 KB (padded 192->196)
    __shared__ __align__(16) float As[16][68];       //  4.25 KB (padded 64->68)
    __shared__ __align__(16) int4   s_off[LL][64];   //  5 KB
    __shared__ __align__(16) float4 s_wt [LL][64];   //  5 KB

    int b  = blockIdx.y;
    int n0 = blockIdx.x * 64;
    int tid = threadIdx.x;
    int tx = tid % 16;        // pixel group: 4 px
    int ty = tid / 16;        // channel group: c0 = ty*4

    // ---- precompute bilinear taps for this block's 64 pixels x 5 levels ----
    for (int i = tid; i < LL * 64; i += 256) {
        int l = i / 64, p = i % 64;
        int pix = n0 + p;
        int gx = pix % WW;
        int gy = pix / WW;

        const float* fl = g_flows + ((size_t)b * CFL + 2 * l) * HW;
        float fx = fl[pix];
        float fy = fl[HW + pix];

        float vx = (float)gx - fx;
        float vy = (float)gy - fy;
        float gxn = 2.f * vx / (float)(WW - 1) - 1.f;
        float gyn = 2.f * vy / (float)(HH - 1) - 1.f;
        float sx = ((gxn + 1.f) * (float)WW - 1.f) * 0.5f;
        float sy = ((gyn + 1.f) * (float)HH - 1.f) * 0.5f;

        float x0f = floorf(sx), y0f = floorf(sy);
        int x0 = (int)x0f, y0 = (int)y0f;
        int x1 = x0 + 1, y1 = y0 + 1;
        float wx1 = sx - x0f, wx0 = 1.f - wx1;
        float wy1 = sy - y0f, wy0 = 1.f - wy1;

        bool vx0 = (x0 >= 0) && (x0 < WW);
        bool vx1 = (x1 >= 0) && (x1 < WW);
        bool vy0 = (y0 >= 0) && (y0 < HH);
        bool vy1 = (y1 >= 0) && (y1 < HH);

        int xc0 = min(max(x0, 0), WW - 1);
        int xc1 = min(max(x1, 0), WW - 1);
        int yc0 = min(max(y0, 0), HH - 1);
        int yc1 = min(max(y1, 0), HH - 1);

        float4 wt;
        wt.x = (vy0 && vx0) ? wy0 * wx0 : 0.f;
        wt.y = (vy0 && vx1) ? wy0 * wx1 : 0.f;
        wt.z = (vy1 && vx0) ? wy1 * wx0 : 0.f;
        wt.w = (vy1 && vx1) ? wy1 * wx1 : 0.f;

        int4 off;
        off.x = yc0 * WW + xc0;
        off.y = yc0 * WW + xc1;
        off.z = yc1 * WW + xc0;
        off.w = yc1 * WW + xc1;

        s_off[l][p] = off;
        s_wt[l][p]  = wt;
    }
    __syncthreads();

    const float* hpb = hp + (size_t)b * NF * HW;

    float acc[3][4][4];       // [component][c][px]
#pragma unroll
    for (int g = 0; g < 3; g++)
#pragma unroll
        for (int i = 0; i < 4; i++)
#pragma unroll
            for (int j = 0; j < 4; j++) acc[g][i][j] = 0.f;

    int arow = tid / 16;      // k-row within tile
    int acol = (tid % 16) * 4;

    for (int k0 = 0; k0 < K; k0 += 16) {
        // ---- stage W directly into smem (12 elems/thread) ----
#pragma unroll
        for (int r = 0; r < 12; r++) {
            int i = tid + r * 256;
            int m = i >> 4, kk = i & 15;
            Ws[kk][m] = Wm[(size_t)m * K + k0 + kk];
        }
        // ---- stage gathered A directly into smem (4 elems/thread) ----
        {
            int l = k0 / 64;
            int c = (k0 & 63) + arow;
            const float* hc = hpb + (size_t)c * HW;
#pragma unroll
            for (int j = 0; j < 4; j++) {
                int p = acol + j;
                int4   o4 = s_off[l][p];
                float4 w4 = s_wt[l][p];
                As[arow][p] = w4.x * __ldg(hc + o4.x) + w4.y * __ldg(hc + o4.y)
                            + w4.z * __ldg(hc + o4.z) + w4.w * __ldg(hc + o4.w);
            }
        }
        __syncthreads();

#pragma unroll
        for (int kk = 0; kk < 16; kk++) {
            float4 a4 = *(const float4*)&As[kk][tx * 4];
            float4 wr = *(const float4*)&Ws[kk][ty * 4];
            float4 wu = *(const float4*)&Ws[kk][ty * 4 + 64];
            float4 wm = *(const float4*)&Ws[kk][ty * 4 + 128];
#define MM(G, WV) { \
            acc[G][0][0] += WV.x*a4.x; acc[G][0][1] += WV.x*a4.y; acc[G][0][2] += WV.x*a4.z; acc[G][0][3] += WV.x*a4.w; \
            acc[G][1][0] += WV.y*a4.x; acc[G][1][1] += WV.y*a4.y; acc[G][1][2] += WV.y*a4.z; acc[G][1][3] += WV.y*a4.w; \
            acc[G][2][0] += WV.z*a4.x; acc[G][2][1] += WV.z*a4.y; acc[G][2][2] += WV.z*a4.z; acc[G][2][3] += WV.z*a4.w; \
            acc[G][3][0] += WV.w*a4.x; acc[G][3][1] += WV.w*a4.y; acc[G][3][2] += WV.w*a4.z; acc[G][3][3] += WV.w*a4.w; }
            MM(0, wr) MM(1, wu) MM(2, wm)
#undef MM
        }
        __syncthreads();   // guard: next tile's staging overwrites Ws/As
    }

    // epilogue: GRU gates for this thread's 4 channels x 4 pixels
    const float* i2h_t = g_i2h + (size_t)t * BB * C3 * HW;
    int np = n0 + tx * 4;

#pragma unroll
    for (int i = 0; i < 4; i++) {
        int c = ty * 4 + i;
        size_t base = ((size_t)b * C3 + c) * HW + np;
        float4 ir = *(const float4*)&i2h_t[base];
        float4 iu = *(const float4*)&i2h_t[base + (size_t)NF * HW];
        float4 im = *(const float4*)&i2h_t[base + (size_t)2 * NF * HW];
        float4 hp4 = *(const float4*)&hp[((size_t)b * NF + c) * HW + np];
        float br = bias[c], bu = bias[c + NF], bm = bias[c + 2 * NF];

        float4 outv;
#define GATE1(X, J) { \
        float r = fsigmoid(ir.X + acc[0][i][J] + br); \
        float u = fsigmoid(iu.X + acc[1][i][J] + bu); \
        float m = ftanh(im.X + r * (acc[2][i][J] + bm)); \
        outv.X = u * hp4.X + (1.f - u) * m; }
        GATE1(x, 0) GATE1(y, 1) GATE1(z, 2) GATE1(w, 3)
#undef GATE1

        *(float4*)&hn[((size_t)b * NF + c) * HW + np] = outv;
    }
}

// ==================== gates for t=0 only (h_prev = 0, h2h = bias) ====================
__global__ void gates_first_kernel(float* __restrict__ hn, const float* __restrict__ ret_b)
{
    int idx = blockIdx.x * blockDim.x + threadIdx.x;
    const int total4 = BB * NF * HW / 4;
    if (idx >= total4) return;

    int e = idx * 4;
    int pix = e % HW;
    int rest = e / HW;
    int c = rest % NF;
    int b = rest / NF;

    const float* i2h_t = g_i2h;   // t = 0
    size_t base = ((size_t)b * C3 + c) * HW + pix;
    float4 ir = *(const float4*)&i2h_t[base];
    float4 iu = *(const float4*)&i2h_t[base + (size_t)NF * HW];
    float4 im = *(const float4*)&i2h_t[base + (size_t)2 * NF * HW];

    float br = ret_b[c], bu = ret_b[c + NF], bm = ret_b[c + 2 * NF];

    float4 outv;
#define GATE1(X) { \
        float r = fsigmoid(ir.X + br); \
        float u = fsigmoid(iu.X + bu); \
        float m = ftanh(im.X + r * bm); \
        outv.X = (1.f - u) * m; }
    GATE1(x) GATE1(y) GATE1(z) GATE1(w)
#undef GATE1

    *(float4*)&hn[((size_t)b * NF + c) * HW + pix] = outv;
}

// -------------------- launcher --------------------
extern "C" void kernel_launch(void* const* d_in, const int* in_sizes, int n_in,
                              void* d_out, int out_size)
{
    const float* inputs  = (const float*)d_in[0];
    const float* i2h_w   = (const float*)d_in[1];
    const float* i2h_b   = (const float*)d_in[2];
    const float* i2f_w   = (const float*)d_in[3];
    const float* i2f_b   = (const float*)d_in[4];
    const float* h2f_w   = (const float*)d_in[5];
    const float* h2f_b   = (const float*)d_in[6];
    const float* flows_w = (const float*)d_in[7];
    const float* flows_b = (const float*)d_in[8];
    const float* ret_w   = (const float*)d_in[9];
    const float* ret_b   = (const float*)d_in[10];
    float* out = (float*)d_out;

    const int hstride = BB * NF * HW;
    const dim3 thr16(16, 16);

    conv3_kernel<<<dim3(9, C3 / 16, SEQ * BB), thr16>>>(inputs, i2h_w, i2h_b);

    for (int t = 0; t < SEQ; t++) {
        const float* x_t   = inputs + (size_t)t * BB * CIN * HW;
        const float* hprev = (t == 0) ? nullptr : out + (size_t)(t - 1) * hstride;
        float* hnew        = out + (size_t)t * hstride;
        int first = (t == 0) ? 1 : 0;

        conv5_f_kernel<<<dim3(9, CF / 8, BB), thr16>>>(x_t, hprev, i2f_w, h2f_w,
                                                       i2f_b, h2f_b, first);

        if (first) {
            gates_first_kernel<<<(hstride / 4 + 255) / 256, 256>>>(hnew, ret_b);
        } else {
            conv5_flows_kernel<<<dim3(9, 1, BB), thr16>>>(flows_w, flows_b);
            warp_gemm_gates_kernel<<<dim3(HW / 64, BB), 256>>>(ret_w, ret_b, t, hprev, hnew);
        }
    }

    if (out_size >= (SEQ + 1) * hstride) {
        copy_kernel<<<(hstride + 255) / 256, 256>>>(out + (size_t)(SEQ - 1) * hstride,
                                                    out + (size_t)SEQ * hstride, hstride);
    }
}

// round 15
// speedup vs baseline: 1.0942x; 1.0026x over previous
#include <cuda_runtime.h>
#include <cuda_bf16.h>
#include <math.h>

// Problem constants (fixed shapes)
#define SEQ   8
#define BB    8
#define CIN   16
#define HH    96
#define WW    96
#define HW    (HH*WW)      // 9216
#define NF    64
#define LL    5
#define C3    (3*NF)       // 192
#define CF    32           // f channels
#define CFL   (2*LL)       // 10 flow channels
#define KW    (LL*NF)      // 320 warped channels

// -------------------- scratch (device globals; no allocation) --------------------
__device__ float g_i2h  [(size_t)SEQ * BB * C3 * HW];
__device__ float g_f    [(size_t)BB * CF  * HW];
__device__ float g_flows[(size_t)BB * CFL * HW];

// fast transcendentals (accuracy budget is 1e-3; these are ~1e-7 level here)
__device__ __forceinline__ float fsigmoid(float x) {
    return 1.f / (1.f + __expf(-x));
}
__device__ __forceinline__ float ftanh(float x) {
    float e = __expf(2.f * x);
    return (e - 1.f) / (e + 1.f);
}

// -------------------- utility --------------------
__global__ void copy_kernel(const float* __restrict__ src, float* __restrict__ dst, int n) {
    int i = blockIdx.x * blockDim.x + threadIdx.x;
    if (i < n) dst[i] = src[i];
}

// ==================== conv3: i2h for ALL timesteps ====================
// 16 oc/block, 2x2 px/thread, 32x32 tile, double-buffered staging.
// grid (9, 12, SEQ*BB), block (16,16)
__global__ void __launch_bounds__(256, 2)
conv3_kernel(const float* __restrict__ x, const float* __restrict__ w,
             const float* __restrict__ bias)
{
    __shared__ __align__(16) float sm[2][34 * 34];
    __shared__ __align__(16) float sw[CIN * 16 * 12];   // [ic][o][12], pad 9->12

    int sb  = blockIdx.z;
    int ocg = blockIdx.y;
    int tileY = (blockIdx.x / 3) * 32;
    int tileX = (blockIdx.x % 3) * 32;
    int tid = threadIdx.y * 16 + threadIdx.x;

    for (int i = tid; i < CIN * 16 * 12; i += 256) {
        int ic = i / 192, rem = i % 192;
        int o = rem / 12, k = rem % 12;
        sw[i] = (k < 9) ? w[((ocg * 16 + o) * CIN + ic) * 9 + k] : 0.f;
    }

    const float* xb = x + (size_t)sb * CIN * HW;

    float rbuf[5];
#define C3_LD(IC) { \
        const float* src = xb + (size_t)(IC) * HW; \
        _Pragma("unroll") \
        for (int k = 0; k < 5; k++) { \
            int i = tid + k * 256; float v = 0.f; \
            if (i < 34 * 34) { \
                int r = i / 34, c = i % 34; \
                int gy = tileY + r - 1, gx = tileX + c - 1; \
                if ((unsigned)gy < (unsigned)HH && (unsigned)gx < (unsigned)WW) \
                    v = src[gy * WW + gx]; \
            } \
            rbuf[k] = v; \
        } }
#define C3_ST(BUF) { \
        _Pragma("unroll") \
        for (int k = 0; k < 5; k++) { \
            int i = tid + k * 256; \
            if (i < 34 * 34) sm[BUF][i] = rbuf[k]; \
        } }

    float acc[16][4];
#pragma unroll
    for (int o = 0; o < 16; o++)
#pragma unroll
        for (int p = 0; p < 4; p++) acc[o][p] = 0.f;

    C3_LD(0);
    int buf = 0;
    for (int ic = 0; ic < CIN; ic++) {
        C3_ST(buf);
        __syncthreads();
        if (ic + 1 < CIN) C3_LD(ic + 1);

        int ry = threadIdx.y * 2, rx = threadIdx.x * 2;
        float win[4][4];
#pragma unroll
        for (int i = 0; i < 4; i++) {
            float2 a = *(const float2*)&sm[buf][(ry + i) * 34 + rx];
            float2 bq = *(const float2*)&sm[buf][(ry + i) * 34 + rx + 2];
            win[i][0] = a.x; win[i][1] = a.y; win[i][2] = bq.x; win[i][3] = bq.y;
        }

#pragma unroll
        for (int o = 0; o < 16; o++) {
            float wv[12];
#pragma unroll
            for (int q = 0; q < 3; q++)
                *(float4*)&wv[q * 4] = *(const float4*)&sw[(ic * 16 + o) * 12 + q * 4];
#pragma unroll
            for (int py = 0; py < 2; py++)
#pragma unroll
                for (int px = 0; px < 2; px++) {
                    acc[o][py*2+px] +=
                        win[py  ][px]*wv[0] + win[py  ][px+1]*wv[1] + win[py  ][px+2]*wv[2]
                      + win[py+1][px]*wv[3] + win[py+1][px+1]*wv[4] + win[py+1][px+2]*wv[5]
                      + win[py+2][px]*wv[6] + win[py+2][px+1]*wv[7] + win[py+2][px+2]*wv[8];
                }
        }
        buf ^= 1;
    }
#undef C3_LD
#undef C3_ST

    int oy = tileY + threadIdx.y * 2, ox = tileX + threadIdx.x * 2;
#pragma unroll
    for (int o = 0; o < 16; o++) {
        float bv = bias[ocg * 16 + o];
        float* yp = g_i2h + ((size_t)sb * C3 + ocg * 16 + o) * HW;
        yp[oy * WW + ox]           = acc[o][0] + bv;
        yp[oy * WW + ox + 1]       = acc[o][1] + bv;
        yp[(oy + 1) * WW + ox]     = acc[o][2] + bv;
        yp[(oy + 1) * WW + ox + 1] = acc[o][3] + bv;
    }
}

// ==================== fused f conv: tanh(conv5(x) + conv5(h_prev)) ====================
// 8 oc/block, 2x2 px/thread, double-buffered; window LDS.64, weights padded 25->28.
// grid (9, 4, BB), block (16,16)
__global__ void __launch_bounds__(256, 2)
conv5_f_kernel(const float* __restrict__ x, const float* __restrict__ hp,
               const float* __restrict__ i2f_w, const float* __restrict__ h2f_w,
               const float* __restrict__ i2f_b, const float* __restrict__ h2f_b,
               int skip_h)
{
    __shared__ __align__(16) float sm[2][36 * 36];
    __shared__ __align__(16) float sw[2][8 * 28];

    int b   = blockIdx.z;
    int ocg = blockIdx.y;
    int tileY = (blockIdx.x / 3) * 32;
    int tileX = (blockIdx.x % 3) * 32;
    int tid = threadIdx.y * 16 + threadIdx.x;

    float acc[8][4];
#pragma unroll
    for (int o = 0; o < 8; o++)
#pragma unroll
        for (int p = 0; p < 4; p++) acc[o][p] = 0.f;

    int ctot = skip_h ? CIN : (CIN + NF);

    float rbuf[6], wreg = 0.f;
#define F_LD(IC) { \
        const float* src; const float* wsrc; int cnum, icl; \
        if ((IC) < CIN) { src = x + ((size_t)b * CIN + (IC)) * HW; wsrc = i2f_w; cnum = CIN; icl = (IC); } \
        else { src = hp + ((size_t)b * NF + ((IC) - CIN)) * HW; wsrc = h2f_w; cnum = NF; icl = (IC) - CIN; } \
        _Pragma("unroll") \
        for (int k = 0; k < 6; k++) { \
            int i = tid + k * 256; float v = 0.f; \
            if (i < 36 * 36) { \
                int r = i / 36, c = i % 36; \
                int gy = tileY + r - 2, gx = tileX + c - 2; \
                if ((unsigned)gy < (unsigned)HH && (unsigned)gx < (unsigned)WW) \
                    v = src[gy * WW + gx]; \
            } \
            rbuf[k] = v; \
        } \
        if (tid < 224) { \
            int o = tid / 28, kk = tid % 28; \
            wreg = (kk < 25) ? wsrc[((size_t)(ocg * 8 + o) * cnum + icl) * 25 + kk] : 0.f; \
        } }
#define F_ST(BUF) { \
        _Pragma("unroll") \
        for (int k = 0; k < 6; k++) { \
            int i = tid + k * 256; \
            if (i < 36 * 36) sm[BUF][i] = rbuf[k]; \
        } \
        if (tid < 224) sw[BUF][tid] = wreg; }

    F_LD(0);
    int buf = 0;
    for (int ic = 0; ic < ctot; ic++) {
        F_ST(buf);
        __syncthreads();
        if (ic + 1 < ctot) F_LD(ic + 1);

        int ry = threadIdx.y * 2, rx = threadIdx.x * 2;
        float win[6][6];
#pragma unroll
        for (int i = 0; i < 6; i++) {
            float2 a = *(const float2*)&sm[buf][(ry + i) * 36 + rx];
            float2 bq = *(const float2*)&sm[buf][(ry + i) * 36 + rx + 2];
            float2 cq = *(const float2*)&sm[buf][(ry + i) * 36 + rx + 4];
            win[i][0] = a.x;  win[i][1] = a.y;
            win[i][2] = bq.x; win[i][3] = bq.y;
            win[i][4] = cq.x; win[i][5] = cq.y;
        }

#pragma unroll
        for (int o = 0; o < 8; o++) {
            float wv[28];
#pragma unroll
            for (int q = 0; q < 7; q++)
                *(float4*)&wv[q * 4] = *(const float4*)&sw[buf][o * 28 + q * 4];
#pragma unroll
            for (int ky = 0; ky < 5; ky++)
#pragma unroll
                for (int kx = 0; kx < 5; kx++) {
                    float wvv = wv[ky * 5 + kx];
                    acc[o][0] += win[ky  ][kx  ] * wvv;
                    acc[o][1] += win[ky  ][kx+1] * wvv;
                    acc[o][2] += win[ky+1][kx  ] * wvv;
                    acc[o][3] += win[ky+1][kx+1] * wvv;
                }
        }
        buf ^= 1;
    }
#undef F_LD
#undef F_ST

    int oy = tileY + threadIdx.y * 2, ox = tileX + threadIdx.x * 2;
#pragma unroll
    for (int o = 0; o < 8; o++) {
        int oc = ocg * 8 + o;
        float bv = i2f_b[oc] + h2f_b[oc];
        float* yp = g_f + ((size_t)b * CF + oc) * HW;
        yp[oy * WW + ox]           = ftanh(acc[o][0] + bv);
        yp[oy * WW + ox + 1]       = ftanh(acc[o][1] + bv);
        yp[(oy + 1) * WW + ox]     = ftanh(acc[o][2] + bv);
        yp[(oy + 1) * WW + ox + 1] = ftanh(acc[o][3] + bv);
    }
}

// ==================== flows conv: conv5(g_f) -> g_flows ====================
// all 10 oc, 2x2 px/thread; all weights preloaded padded.
// grid (9, 1, BB), block (16,16)
__global__ void __launch_bounds__(256, 2)
conv5_flows_kernel(const float* __restrict__ flows_w, const float* __restrict__ flows_b)
{
    __shared__ __align__(16) float sm[2][36 * 36];
    __shared__ __align__(16) float sw[CFL * CF * 28];

    int b = blockIdx.z;
    int tileY = (blockIdx.x / 3) * 32;
    int tileX = (blockIdx.x % 3) * 32;
    int tid = threadIdx.y * 16 + threadIdx.x;

    for (int i = tid; i < CFL * CF * 28; i += 256) {
        int k = i % 28;
        int oc_ic = i / 28;
        sw[i] = (k < 25) ? flows_w[oc_ic * 25 + k] : 0.f;
    }

    float acc[CFL][4];
#pragma unroll
    for (int o = 0; o < CFL; o++)
#pragma unroll
        for (int p = 0; p < 4; p++) acc[o][p] = 0.f;

    float rbuf[6];
#define FL_LD(IC) { \
        const float* src = g_f + ((size_t)b * CF + (IC)) * HW; \
        _Pragma("unroll") \
        for (int k = 0; k < 6; k++) { \
            int i = tid + k * 256; float v = 0.f; \
            if (i < 36 * 36) { \
                int r = i / 36, c = i % 36; \
                int gy = tileY + r - 2, gx = tileX + c - 2; \
                if ((unsigned)gy < (unsigned)HH && (unsigned)gx < (unsigned)WW) \
                    v = src[gy * WW + gx]; \
            } \
            rbuf[k] = v; \
        } }
#define FL_ST(BUF) { \
        _Pragma("unroll") \
        for (int k = 0; k < 6; k++) { \
            int i = tid + k * 256; \
            if (i < 36 * 36) sm[BUF][i] = rbuf[k]; \
        } }

    FL_LD(0);
    int buf = 0;
    for (int ic = 0; ic < CF; ic++) {
        FL_ST(buf);
        __syncthreads();
        if (ic + 1 < CF) FL_LD(ic + 1);

        int ry = threadIdx.y * 2, rx = threadIdx.x * 2;
        float win[6][6];
#pragma unroll
        for (int i = 0; i < 6; i++) {
            float2 a = *(const float2*)&sm[buf][(ry + i) * 36 + rx];
            float2 bq = *(const float2*)&sm[buf][(ry + i) * 36 + rx + 2];
            float2 cq = *(const float2*)&sm[buf][(ry + i) * 36 + rx + 4];
            win[i][0] = a.x;  win[i][1] = a.y;
            win[i][2] = bq.x; win[i][3] = bq.y;
            win[i][4] = cq.x; win[i][5] = cq.y;
        }

#pragma unroll
        for (int o = 0; o < CFL; o++) {
            float wv[28];
#pragma unroll
            for (int q = 0; q < 7; q++)
                *(float4*)&wv[q * 4] = *(const float4*)&sw[(o * CF + ic) * 28 + q * 4];
#pragma unroll
            for (int ky = 0; ky < 5; ky++)
#pragma unroll
                for (int kx = 0; kx < 5; kx++) {
                    float wvv = wv[ky * 5 + kx];
                    acc[o][0] += win[ky  ][kx  ] * wvv;
                    acc[o][1] += win[ky  ][kx+1] * wvv;
                    acc[o][2] += win[ky+1][kx  ] * wvv;
                    acc[o][3] += win[ky+1][kx+1] * wvv;
                }
        }
        buf ^= 1;
    }
#undef FL_LD
#undef FL_ST

    int oy = tileY + threadIdx.y * 2, ox = tileX + threadIdx.x * 2;
#pragma unroll
    for (int o = 0; o < CFL; o++) {
        float bv = flows_b[o];
        float* yp = g_flows + ((size_t)b * CFL + o) * HW;
        yp[oy * WW + ox]           = acc[o][0] + bv;
        yp[oy * WW + ox + 1]       = acc[o][1] + bv;
        yp[(oy + 1) * WW + ox]     = acc[o][2] + bv;
        yp[(oy + 1) * WW + ox + 1] = acc[o][3] + bv;
    }
}

// ==================== fused warp + GEMM + gates (v3: BK=32) ====================
// Single-buffer, two-sync staging with BK=32: 10 k-tiles instead of 20, halving
// both staging-latency exposure and sync count while keeping the no-spill live
// set (staging writes straight to smem; accumulators unchanged at 48/thread).
// Each 32-row k-tile still lies within one flow level (64 % 32 == 0).
// BM=192, BN=64; grid (144, BB), block 256.
__global__ void __launch_bounds__(256, 2)
warp_gemm_gates_kernel(const float* __restrict__ Wm, const float* __restrict__ bias,
                       int t, const float* __restrict__ hp, float* __restrict__ hn)
{
    const int K = KW, N = HW;
    __shared__ __align__(16) float Ws[32][196];      // 24.5 KB (padded 192->196)
    __shared__ __align__(16) float As[32][68];       //  8.5 KB (padded 64->68)
    __shared__ __align__(16) int4   s_off[LL][64];   //  5 KB
    __shared__ __align__(16) float4 s_wt [LL][64];   //  5 KB

    int b  = blockIdx.y;
    int n0 = blockIdx.x * 64;
    int tid = threadIdx.x;
    int tx = tid % 16;        // pixel group: 4 px
    int ty = tid / 16;        // channel group: c0 = ty*4

    // ---- precompute bilinear taps for this block's 64 pixels x 5 levels ----
    for (int i = tid; i < LL * 64; i += 256) {
        int l = i / 64, p = i % 64;
        int pix = n0 + p;
        int gx = pix % WW;
        int gy = pix / WW;

        const float* fl = g_flows + ((size_t)b * CFL + 2 * l) * HW;
        float fx = fl[pix];
        float fy = fl[HW + pix];

        float vx = (float)gx - fx;
        float vy = (float)gy - fy;
        float gxn = 2.f * vx / (float)(WW - 1) - 1.f;
        float gyn = 2.f * vy / (float)(HH - 1) - 1.f;
        float sx = ((gxn + 1.f) * (float)WW - 1.f) * 0.5f;
        float sy = ((gyn + 1.f) * (float)HH - 1.f) * 0.5f;

        float x0f = floorf(sx), y0f = floorf(sy);
        int x0 = (int)x0f, y0 = (int)y0f;
        int x1 = x0 + 1, y1 = y0 + 1;
        float wx1 = sx - x0f, wx0 = 1.f - wx1;
        float wy1 = sy - y0f, wy0 = 1.f - wy1;

        bool vx0 = (x0 >= 0) && (x0 < WW);
        bool vx1 = (x1 >= 0) && (x1 < WW);
        bool vy0 = (y0 >= 0) && (y0 < HH);
        bool vy1 = (y1 >= 0) && (y1 < HH);

        int xc0 = min(max(x0, 0), WW - 1);
        int xc1 = min(max(x1, 0), WW - 1);
        int yc0 = min(max(y0, 0), HH - 1);
        int yc1 = min(max(y1, 0), HH - 1);

        float4 wt;
        wt.x = (vy0 && vx0) ? wy0 * wx0 : 0.f;
        wt.y = (vy0 && vx1) ? wy0 * wx1 : 0.f;
        wt.z = (vy1 && vx0) ? wy1 * wx0 : 0.f;
        wt.w = (vy1 && vx1) ? wy1 * wx1 : 0.f;

        int4 off;
        off.x = yc0 * WW + xc0;
        off.y = yc0 * WW + xc1;
        off.z = yc1 * WW + xc0;
        off.w = yc1 * WW + xc1;

        s_off[l][p] = off;
        s_wt[l][p]  = wt;
    }
    __syncthreads();

    const float* hpb = hp + (size_t)b * NF * HW;

    float acc[3][4][4];       // [component][c][px]
#pragma unroll
    for (int g = 0; g < 3; g++)
#pragma unroll
        for (int i = 0; i < 4; i++)
#pragma unroll
            for (int j = 0; j < 4; j++) acc[g][i][j] = 0.f;

    int arow = tid / 16;      // 0..15
    int acol = (tid % 16) * 4;

    for (int k0 = 0; k0 < K; k0 += 32) {
        // ---- stage W directly into smem (24 elems/thread; 32x192 total) ----
#pragma unroll
        for (int r = 0; r < 24; r++) {
            int i = tid + r * 256;
            int m = i >> 5, kk = i & 31;
            Ws[kk][m] = Wm[(size_t)m * K + k0 + kk];
        }
        // ---- stage gathered A directly into smem (2 rows x 4 px per thread) ----
        {
            int l = k0 / 64;
#pragma unroll
            for (int h = 0; h < 2; h++) {
                int r2 = arow + h * 16;
                int c = (k0 & 63) + r2;
                const float* hc = hpb + (size_t)c * HW;
#pragma unroll
                for (int j = 0; j < 4; j++) {
                    int p = acol + j;
                    int4   o4 = s_off[l][p];
                    float4 w4 = s_wt[l][p];
                    As[r2][p] = w4.x * __ldg(hc + o4.x) + w4.y * __ldg(hc + o4.y)
                              + w4.z * __ldg(hc + o4.z) + w4.w * __ldg(hc + o4.w);
                }
            }
        }
        __syncthreads();

#pragma unroll
        for (int kk = 0; kk < 32; kk++) {
            float4 a4 = *(const float4*)&As[kk][tx * 4];
            float4 wr = *(const float4*)&Ws[kk][ty * 4];
            float4 wu = *(const float4*)&Ws[kk][ty * 4 + 64];
            float4 wm = *(const float4*)&Ws[kk][ty * 4 + 128];
#define MM(G, WV) { \
            acc[G][0][0] += WV.x*a4.x; acc[G][0][1] += WV.x*a4.y; acc[G][0][2] += WV.x*a4.z; acc[G][0][3] += WV.x*a4.w; \
            acc[G][1][0] += WV.y*a4.x; acc[G][1][1] += WV.y*a4.y; acc[G][1][2] += WV.y*a4.z; acc[G][1][3] += WV.y*a4.w; \
            acc[G][2][0] += WV.z*a4.x; acc[G][2][1] += WV.z*a4.y; acc[G][2][2] += WV.z*a4.z; acc[G][2][3] += WV.z*a4.w; \
            acc[G][3][0] += WV.w*a4.x; acc[G][3][1] += WV.w*a4.y; acc[G][3][2] += WV.w*a4.z; acc[G][3][3] += WV.w*a4.w; }
            MM(0, wr) MM(1, wu) MM(2, wm)
#undef MM
        }
        __syncthreads();   // guard: next tile's staging overwrites Ws/As
    }

    // epilogue: GRU gates for this thread's 4 channels x 4 pixels
    const float* i2h_t = g_i2h + (size_t)t * BB * C3 * HW;
    int np = n0 + tx * 4;

#pragma unroll
    for (int i = 0; i < 4; i++) {
        int c = ty * 4 + i;
        size_t base = ((size_t)b * C3 + c) * HW + np;
        float4 ir = *(const float4*)&i2h_t[base];
        float4 iu = *(const float4*)&i2h_t[base + (size_t)NF * HW];
        float4 im = *(const float4*)&i2h_t[base + (size_t)2 * NF * HW];
        float4 hp4 = *(const float4*)&hp[((size_t)b * NF + c) * HW + np];
        float br = bias[c], bu = bias[c + NF], bm = bias[c + 2 * NF];

        float4 outv;
#define GATE1(X, J) { \
        float r = fsigmoid(ir.X + acc[0][i][J] + br); \
        float u = fsigmoid(iu.X + acc[1][i][J] + bu); \
        float m = ftanh(im.X + r * (acc[2][i][J] + bm)); \
        outv.X = u * hp4.X + (1.f - u) * m; }
        GATE1(x, 0) GATE1(y, 1) GATE1(z, 2) GATE1(w, 3)
#undef GATE1

        *(float4*)&hn[((size_t)b * NF + c) * HW + np] = outv;
    }
}

// ==================== gates for t=0 only (h_prev = 0, h2h = bias) ====================
__global__ void gates_first_kernel(float* __restrict__ hn, const float* __restrict__ ret_b)
{
    int idx = blockIdx.x * blockDim.x + threadIdx.x;
    const int total4 = BB * NF * HW / 4;
    if (idx >= total4) return;

    int e = idx * 4;
    int pix = e % HW;
    int rest = e / HW;
    int c = rest % NF;
    int b = rest / NF;

    const float* i2h_t = g_i2h;   // t = 0
    size_t base = ((size_t)b * C3 + c) * HW + pix;
    float4 ir = *(const float4*)&i2h_t[base];
    float4 iu = *(const float4*)&i2h_t[base + (size_t)NF * HW];
    float4 im = *(const float4*)&i2h_t[base + (size_t)2 * NF * HW];

    float br = ret_b[c], bu = ret_b[c + NF], bm = ret_b[c + 2 * NF];

    float4 outv;
#define GATE1(X) { \
        float r = fsigmoid(ir.X + br); \
        float u = fsigmoid(iu.X + bu); \
        float m = ftanh(im.X + r * bm); \
        outv.X = (1.f - u) * m; }
    GATE1(x) GATE1(y) GATE1(z) GATE1(w)
#undef GATE1

    *(float4*)&hn[((size_t)b * NF + c) * HW + pix] = outv;
}

// -------------------- launcher --------------------
extern "C" void kernel_launch(void* const* d_in, const int* in_sizes, int n_in,
                              void* d_out, int out_size)
{
    const float* inputs  = (const float*)d_in[0];
    const float* i2h_w   = (const float*)d_in[1];
    const float* i2h_b   = (const float*)d_in[2];
    const float* i2f_w   = (const float*)d_in[3];
    const float* i2f_b   = (const float*)d_in[4];
    const float* h2f_w   = (const float*)d_in[5];
    const float* h2f_b   = (const float*)d_in[6];
    const float* flows_w = (const float*)d_in[7];
    const float* flows_b = (const float*)d_in[8];
    const float* ret_w   = (const float*)d_in[9];
    const float* ret_b   = (const float*)d_in[10];
    float* out = (float*)d_out;

    const int hstride = BB * NF * HW;
    const dim3 thr16(16, 16);

    conv3_kernel<<<dim3(9, C3 / 16, SEQ * BB), thr16>>>(inputs, i2h_w, i2h_b);

    for (int t = 0; t < SEQ; t++) {
        const float* x_t   = inputs + (size_t)t * BB * CIN * HW;
        const float* hprev = (t == 0) ? nullptr : out + (size_t)(t - 1) * hstride;
        float* hnew        = out + (size_t)t * hstride;
        int first = (t == 0) ? 1 : 0;

        conv5_f_kernel<<<dim3(9, CF / 8, BB), thr16>>>(x_t, hprev, i2f_w, h2f_w,
                                                       i2f_b, h2f_b, first);

        if (first) {
            gates_first_kernel<<<(hstride / 4 + 255) / 256, 256>>>(hnew, ret_b);
        } else {
            conv5_flows_kernel<<<dim3(9, 1, BB), thr16>>>(flows_w, flows_b);
            warp_gemm_gates_kernel<<<dim3(HW / 64, BB), 256>>>(ret_w, ret_b, t, hprev, hnew);
        }
    }

    if (out_size >= (SEQ + 1) * hstride) {
        copy_kernel<<<(hstride + 255) / 256, 256>>>(out + (size_t)(SEQ - 1) * hstride,
                                                    out + (size_t)SEQ * hstride, hstride);
    }
}

// round 16
// speedup vs baseline: 1.1348x; 1.0372x over previous
#include <cuda_runtime.h>
#include <cuda_bf16.h>
#include <math.h>

// Problem constants (fixed shapes)
#define SEQ   8
#define BB    8
#define CIN   16
#define HH    96
#define WW    96
#define HW    (HH*WW)      // 9216
#define NF    64
#define LL    5
#define C3    (3*NF)       // 192
#define CF    32           // f channels
#define CFL   (2*LL)       // 10 flow channels
#define KW    (LL*NF)      // 320 warped channels

// -------------------- scratch (device globals; no allocation) --------------------
__device__ float g_i2h  [(size_t)SEQ * BB * C3 * HW];
__device__ float g_f    [(size_t)BB * CF  * HW];
__device__ float g_flows[(size_t)BB * CFL * HW];

// fast transcendentals (accuracy budget is 1e-3; these are ~1e-7 level here)
__device__ __forceinline__ float fsigmoid(float x) {
    return 1.f / (1.f + __expf(-x));
}
__device__ __forceinline__ float ftanh(float x) {
    float e = __expf(2.f * x);
    return (e - 1.f) / (e + 1.f);
}

// -------------------- utility --------------------
__global__ void copy_kernel(const float* __restrict__ src, float* __restrict__ dst, int n) {
    int i = blockIdx.x * blockDim.x + threadIdx.x;
    if (i < n) dst[i] = src[i];
}

// ==================== conv3: i2h for ALL timesteps ====================
// 16 oc/block, 2x2 px/thread, 32x32 tile, double-buffered staging.
// grid (9, 12, SEQ*BB), block (16,16)
__global__ void __launch_bounds__(256, 2)
conv3_kernel(const float* __restrict__ x, const float* __restrict__ w,
             const float* __restrict__ bias)
{
    __shared__ __align__(16) float sm[2][34 * 34];
    __shared__ __align__(16) float sw[CIN * 16 * 12];   // [ic][o][12], pad 9->12

    int sb  = blockIdx.z;
    int ocg = blockIdx.y;
    int tileY = (blockIdx.x / 3) * 32;
    int tileX = (blockIdx.x % 3) * 32;
    int tid = threadIdx.y * 16 + threadIdx.x;

    for (int i = tid; i < CIN * 16 * 12; i += 256) {
        int ic = i / 192, rem = i % 192;
        int o = rem / 12, k = rem % 12;
        sw[i] = (k < 9) ? w[((ocg * 16 + o) * CIN + ic) * 9 + k] : 0.f;
    }

    const float* xb = x + (size_t)sb * CIN * HW;

    float rbuf[5];
#define C3_LD(IC) { \
        const float* src = xb + (size_t)(IC) * HW; \
        _Pragma("unroll") \
        for (int k = 0; k < 5; k++) { \
            int i = tid + k * 256; float v = 0.f; \
            if (i < 34 * 34) { \
                int r = i / 34, c = i % 34; \
                int gy = tileY + r - 1, gx = tileX + c - 1; \
                if ((unsigned)gy < (unsigned)HH && (unsigned)gx < (unsigned)WW) \
                    v = src[gy * WW + gx]; \
            } \
            rbuf[k] = v; \
        } }
#define C3_ST(BUF) { \
        _Pragma("unroll") \
        for (int k = 0; k < 5; k++) { \
            int i = tid + k * 256; \
            if (i < 34 * 34) sm[BUF][i] = rbuf[k]; \
        } }

    float acc[16][4];
#pragma unroll
    for (int o = 0; o < 16; o++)
#pragma unroll
        for (int p = 0; p < 4; p++) acc[o][p] = 0.f;

    C3_LD(0);
    int buf = 0;
    for (int ic = 0; ic < CIN; ic++) {
        C3_ST(buf);
        __syncthreads();
        if (ic + 1 < CIN) C3_LD(ic + 1);

        int ry = threadIdx.y * 2, rx = threadIdx.x * 2;
        float win[4][4];
#pragma unroll
        for (int i = 0; i < 4; i++) {
            float2 a = *(const float2*)&sm[buf][(ry + i) * 34 + rx];
            float2 bq = *(const float2*)&sm[buf][(ry + i) * 34 + rx + 2];
            win[i][0] = a.x; win[i][1] = a.y; win[i][2] = bq.x; win[i][3] = bq.y;
        }

#pragma unroll
        for (int o = 0; o < 16; o++) {
            float wv[12];
#pragma unroll
            for (int q = 0; q < 3; q++)
                *(float4*)&wv[q * 4] = *(const float4*)&sw[(ic * 16 + o) * 12 + q * 4];
#pragma unroll
            for (int py = 0; py < 2; py++)
#pragma unroll
                for (int px = 0; px < 2; px++) {
                    acc[o][py*2+px] +=
                        win[py  ][px]*wv[0] + win[py  ][px+1]*wv[1] + win[py  ][px+2]*wv[2]
                      + win[py+1][px]*wv[3] + win[py+1][px+1]*wv[4] + win[py+1][px+2]*wv[5]
                      + win[py+2][px]*wv[6] + win[py+2][px+1]*wv[7] + win[py+2][px+2]*wv[8];
                }
        }
        buf ^= 1;
    }
#undef C3_LD
#undef C3_ST

    int oy = tileY + threadIdx.y * 2, ox = tileX + threadIdx.x * 2;
#pragma unroll
    for (int o = 0; o < 16; o++) {
        float bv = bias[ocg * 16 + o];
        float* yp = g_i2h + ((size_t)sb * C3 + ocg * 16 + o) * HW;
        yp[oy * WW + ox]           = acc[o][0] + bv;
        yp[oy * WW + ox + 1]       = acc[o][1] + bv;
        yp[(oy + 1) * WW + ox]     = acc[o][2] + bv;
        yp[(oy + 1) * WW + ox + 1] = acc[o][3] + bv;
    }
}

// ==================== fused f conv: tanh(conv5(x) + conv5(h_prev)) ====================
// 8 oc/block, 2x2 px/thread, double-buffered; window LDS.64, weights padded 25->28.
// grid (9, 4, BB), block (16,16)
__global__ void __launch_bounds__(256, 2)
conv5_f_kernel(const float* __restrict__ x, const float* __restrict__ hp,
               const float* __restrict__ i2f_w, const float* __restrict__ h2f_w,
               const float* __restrict__ i2f_b, const float* __restrict__ h2f_b,
               int skip_h)
{
    __shared__ __align__(16) float sm[2][36 * 36];
    __shared__ __align__(16) float sw[2][8 * 28];

    int b   = blockIdx.z;
    int ocg = blockIdx.y;
    int tileY = (blockIdx.x / 3) * 32;
    int tileX = (blockIdx.x % 3) * 32;
    int tid = threadIdx.y * 16 + threadIdx.x;

    float acc[8][4];
#pragma unroll
    for (int o = 0; o < 8; o++)
#pragma unroll
        for (int p = 0; p < 4; p++) acc[o][p] = 0.f;

    int ctot = skip_h ? CIN : (CIN + NF);

    float rbuf[6], wreg = 0.f;
#define F_LD(IC) { \
        const float* src; const float* wsrc; int cnum, icl; \
        if ((IC) < CIN) { src = x + ((size_t)b * CIN + (IC)) * HW; wsrc = i2f_w; cnum = CIN; icl = (IC); } \
        else { src = hp + ((size_t)b * NF + ((IC) - CIN)) * HW; wsrc = h2f_w; cnum = NF; icl = (IC) - CIN; } \
        _Pragma("unroll") \
        for (int k = 0; k < 6; k++) { \
            int i = tid + k * 256; float v = 0.f; \
            if (i < 36 * 36) { \
                int r = i / 36, c = i % 36; \
                int gy = tileY + r - 2, gx = tileX + c - 2; \
                if ((unsigned)gy < (unsigned)HH && (unsigned)gx < (unsigned)WW) \
                    v = src[gy * WW + gx]; \
            } \
            rbuf[k] = v; \
        } \
        if (tid < 224) { \
            int o = tid / 28, kk = tid % 28; \
            wreg = (kk < 25) ? wsrc[((size_t)(ocg * 8 + o) * cnum + icl) * 25 + kk] : 0.f; \
        } }
#define F_ST(BUF) { \
        _Pragma("unroll") \
        for (int k = 0; k < 6; k++) { \
            int i = tid + k * 256; \
            if (i < 36 * 36) sm[BUF][i] = rbuf[k]; \
        } \
        if (tid < 224) sw[BUF][tid] = wreg; }

    F_LD(0);
    int buf = 0;
    for (int ic = 0; ic < ctot; ic++) {
        F_ST(buf);
        __syncthreads();
        if (ic + 1 < ctot) F_LD(ic + 1);

        int ry = threadIdx.y * 2, rx = threadIdx.x * 2;
        float win[6][6];
#pragma unroll
        for (int i = 0; i < 6; i++) {
            float2 a = *(const float2*)&sm[buf][(ry + i) * 36 + rx];
            float2 bq = *(const float2*)&sm[buf][(ry + i) * 36 + rx + 2];
            float2 cq = *(const float2*)&sm[buf][(ry + i) * 36 + rx + 4];
            win[i][0] = a.x;  win[i][1] = a.y;
            win[i][2] = bq.x; win[i][3] = bq.y;
            win[i][4] = cq.x; win[i][5] = cq.y;
        }

#pragma unroll
        for (int o = 0; o < 8; o++) {
            float wv[28];
#pragma unroll
            for (int q = 0; q < 7; q++)
                *(float4*)&wv[q * 4] = *(const float4*)&sw[buf][o * 28 + q * 4];
#pragma unroll
            for (int ky = 0; ky < 5; ky++)
#pragma unroll
                for (int kx = 0; kx < 5; kx++) {
                    float wvv = wv[ky * 5 + kx];
                    acc[o][0] += win[ky  ][kx  ] * wvv;
                    acc[o][1] += win[ky  ][kx+1] * wvv;
                    acc[o][2] += win[ky+1][kx  ] * wvv;
                    acc[o][3] += win[ky+1][kx+1] * wvv;
                }
        }
        buf ^= 1;
    }
#undef F_LD
#undef F_ST

    int oy = tileY + threadIdx.y * 2, ox = tileX + threadIdx.x * 2;
#pragma unroll
    for (int o = 0; o < 8; o++) {
        int oc = ocg * 8 + o;
        float bv = i2f_b[oc] + h2f_b[oc];
        float* yp = g_f + ((size_t)b * CF + oc) * HW;
        yp[oy * WW + ox]           = ftanh(acc[o][0] + bv);
        yp[oy * WW + ox + 1]       = ftanh(acc[o][1] + bv);
        yp[(oy + 1) * WW + ox]     = ftanh(acc[o][2] + bv);
        yp[(oy + 1) * WW + ox + 1] = ftanh(acc[o][3] + bv);
    }
}

// ==================== flows conv: conv5(g_f) -> g_flows ====================
// SPLIT into 2 oc-groups of 5 for full-chip parallelism (was 72 blocks -> 144).
// 2x2 px/thread; group's weights preloaded padded. grid (9, 2, BB), block (16,16)
#define FL_OCG 5
__global__ void __launch_bounds__(256, 2)
conv5_flows_kernel(const float* __restrict__ flows_w, const float* __restrict__ flows_b)
{
    __shared__ __align__(16) float sm[2][36 * 36];
    __shared__ __align__(16) float sw[FL_OCG * CF * 28];

    int b   = blockIdx.z;
    int ocg = blockIdx.y;          // 0 or 1
    int oc0 = ocg * FL_OCG;
    int tileY = (blockIdx.x / 3) * 32;
    int tileX = (blockIdx.x % 3) * 32;
    int tid = threadIdx.y * 16 + threadIdx.x;

    for (int i = tid; i < FL_OCG * CF * 28; i += 256) {
        int k = i % 28;
        int oc_ic = i / 28;        // o*CF + ic, o in [0,5)
        int o = oc_ic / CF, ic = oc_ic % CF;
        sw[i] = (k < 25) ? flows_w[((oc0 + o) * CF + ic) * 25 + k] : 0.f;
    }

    float acc[FL_OCG][4];
#pragma unroll
    for (int o = 0; o < FL_OCG; o++)
#pragma unroll
        for (int p = 0; p < 4; p++) acc[o][p] = 0.f;

    float rbuf[6];
#define FL_LD(IC) { \
        const float* src = g_f + ((size_t)b * CF + (IC)) * HW; \
        _Pragma("unroll") \
        for (int k = 0; k < 6; k++) { \
            int i = tid + k * 256; float v = 0.f; \
            if (i < 36 * 36) { \
                int r = i / 36, c = i % 36; \
                int gy = tileY + r - 2, gx = tileX + c - 2; \
                if ((unsigned)gy < (unsigned)HH && (unsigned)gx < (unsigned)WW) \
                    v = src[gy * WW + gx]; \
            } \
            rbuf[k] = v; \
        } }
#define FL_ST(BUF) { \
        _Pragma("unroll") \
        for (int k = 0; k < 6; k++) { \
            int i = tid + k * 256; \
            if (i < 36 * 36) sm[BUF][i] = rbuf[k]; \
        } }

    FL_LD(0);
    int buf = 0;
    for (int ic = 0; ic < CF; ic++) {
        FL_ST(buf);
        __syncthreads();
        if (ic + 1 < CF) FL_LD(ic + 1);

        int ry = threadIdx.y * 2, rx = threadIdx.x * 2;
        float win[6][6];
#pragma unroll
        for (int i = 0; i < 6; i++) {
            float2 a = *(const float2*)&sm[buf][(ry + i) * 36 + rx];
            float2 bq = *(const float2*)&sm[buf][(ry + i) * 36 + rx + 2];
            float2 cq = *(const float2*)&sm[buf][(ry + i) * 36 + rx + 4];
            win[i][0] = a.x;  win[i][1] = a.y;
            win[i][2] = bq.x; win[i][3] = bq.y;
            win[i][4] = cq.x; win[i][5] = cq.y;
        }

#pragma unroll
        for (int o = 0; o < FL_OCG; o++) {
            float wv[28];
#pragma unroll
            for (int q = 0; q < 7; q++)
                *(float4*)&wv[q * 4] = *(const float4*)&sw[(o * CF + ic) * 28 + q * 4];
#pragma unroll
            for (int ky = 0; ky < 5; ky++)
#pragma unroll
                for (int kx = 0; kx < 5; kx++) {
                    float wvv = wv[ky * 5 + kx];
                    acc[o][0] += win[ky  ][kx  ] * wvv;
                    acc[o][1] += win[ky  ][kx+1] * wvv;
                    acc[o][2] += win[ky+1][kx  ] * wvv;
                    acc[o][3] += win[ky+1][kx+1] * wvv;
                }
        }
        buf ^= 1;
    }
#undef FL_LD
#undef FL_ST

    int oy = tileY + threadIdx.y * 2, ox = tileX + threadIdx.x * 2;
#pragma unroll
    for (int o = 0; o < FL_OCG; o++) {
        float bv = flows_b[oc0 + o];
        float* yp = g_flows + ((size_t)b * CFL + oc0 + o) * HW;
        yp[oy * WW + ox]           = acc[o][0] + bv;
        yp[oy * WW + ox + 1]       = acc[o][1] + bv;
        yp[(oy + 1) * WW + ox]     = acc[o][2] + bv;
        yp[(oy + 1) * WW + ox + 1] = acc[o][3] + bv;
    }
}

// ==================== fused warp + GEMM + gates (BK=32) ====================
// Single-buffer, two-sync staging with BK=32. Gathered-A and W staged straight
// to smem (no spill); each 32-row k-tile lies within one flow level.
// BM=192, BN=64; grid (144, BB), block 256.
__global__ void __launch_bounds__(256, 2)
warp_gemm_gates_kernel(const float* __restrict__ Wm, const float* __restrict__ bias,
                       int t, const float* __restrict__ hp, float* __restrict__ hn)
{
    const int K = KW, N = HW;
    __shared__ __align__(16) float Ws[32][196];      // 24.5 KB (padded 192->196)
    __shared__ __align__(16) float As[32][68];       //  8.5 KB (padded 64->68)
    __shared__ __align__(16) int4   s_off[LL][64];   //  5 KB
    __shared__ __align__(16) float4 s_wt [LL][64];   //  5 KB

    int b  = blockIdx.y;
    int n0 = blockIdx.x * 64;
    int tid = threadIdx.x;
    int tx = tid % 16;        // pixel group: 4 px
    int ty = tid / 16;        // channel group: c0 = ty*4

    // ---- precompute bilinear taps for this block's 64 pixels x 5 levels ----
    for (int i = tid; i < LL * 64; i += 256) {
        int l = i / 64, p = i % 64;
        int pix = n0 + p;
        int gx = pix % WW;
        int gy = pix / WW;

        const float* fl = g_flows + ((size_t)b * CFL + 2 * l) * HW;
        float fx = fl[pix];
        float fy = fl[HW + pix];

        float vx = (float)gx - fx;
        float vy = (float)gy - fy;
        float gxn = 2.f * vx / (float)(WW - 1) - 1.f;
        float gyn = 2.f * vy / (float)(HH - 1) - 1.f;
        float sx = ((gxn + 1.f) * (float)WW - 1.f) * 0.5f;
        float sy = ((gyn + 1.f) * (float)HH - 1.f) * 0.5f;

        float x0f = floorf(sx), y0f = floorf(sy);
        int x0 = (int)x0f, y0 = (int)y0f;
        int x1 = x0 + 1, y1 = y0 + 1;
        float wx1 = sx - x0f, wx0 = 1.f - wx1;
        float wy1 = sy - y0f, wy0 = 1.f - wy1;

        bool vx0 = (x0 >= 0) && (x0 < WW);
        bool vx1 = (x1 >= 0) && (x1 < WW);
        bool vy0 = (y0 >= 0) && (y0 < HH);
        bool vy1 = (y1 >= 0) && (y1 < HH);

        int xc0 = min(max(x0, 0), WW - 1);
        int xc1 = min(max(x1, 0), WW - 1);
        int yc0 = min(max(y0, 0), HH - 1);
        int yc1 = min(max(y1, 0), HH - 1);

        float4 wt;
        wt.x = (vy0 && vx0) ? wy0 * wx0 : 0.f;
        wt.y = (vy0 && vx1) ? wy0 * wx1 : 0.f;
        wt.z = (vy1 && vx0) ? wy1 * wx0 : 0.f;
        wt.w = (vy1 && vx1) ? wy1 * wx1 : 0.f;

        int4 off;
        off.x = yc0 * WW + xc0;
        off.y = yc0 * WW + xc1;
        off.z = yc1 * WW + xc0;
        off.w = yc1 * WW + xc1;

        s_off[l][p] = off;
        s_wt[l][p]  = wt;
    }
    __syncthreads();

    const float* hpb = hp + (size_t)b * NF * HW;

    float acc[3][4][4];       // [component][c][px]
#pragma unroll
    for (int g = 0; g < 3; g++)
#pragma unroll
        for (int i = 0; i < 4; i++)
#pragma unroll
            for (int j = 0; j < 4; j++) acc[g][i][j] = 0.f;

    int arow = tid / 16;      // 0..15
    int acol = (tid % 16) * 4;

    for (int k0 = 0; k0 < K; k0 += 32) {
        // ---- stage W directly into smem (24 elems/thread; 32x192 total) ----
#pragma unroll
        for (int r = 0; r < 24; r++) {
            int i = tid + r * 256;
            int m = i >> 5, kk = i & 31;
            Ws[kk][m] = Wm[(size_t)m * K + k0 + kk];
        }
        // ---- stage gathered A directly into smem (2 rows x 4 px per thread) ----
        {
            int l = k0 / 64;
#pragma unroll
            for (int h = 0; h < 2; h++) {
                int r2 = arow + h * 16;
                int c = (k0 & 63) + r2;
                const float* hc = hpb + (size_t)c * HW;
#pragma unroll
                for (int j = 0; j < 4; j++) {
                    int p = acol + j;
                    int4   o4 = s_off[l][p];
                    float4 w4 = s_wt[l][p];
                    As[r2][p] = w4.x * __ldg(hc + o4.x) + w4.y * __ldg(hc + o4.y)
                              + w4.z * __ldg(hc + o4.z) + w4.w * __ldg(hc + o4.w);
                }
            }
        }
        __syncthreads();

#pragma unroll
        for (int kk = 0; kk < 32; kk++) {
            float4 a4 = *(const float4*)&As[kk][tx * 4];
            float4 wr = *(const float4*)&Ws[kk][ty * 4];
            float4 wu = *(const float4*)&Ws[kk][ty * 4 + 64];
            float4 wm = *(const float4*)&Ws[kk][ty * 4 + 128];
#define MM(G, WV) { \
            acc[G][0][0] += WV.x*a4.x; acc[G][0][1] += WV.x*a4.y; acc[G][0][2] += WV.x*a4.z; acc[G][0][3] += WV.x*a4.w; \
            acc[G][1][0] += WV.y*a4.x; acc[G][1][1] += WV.y*a4.y; acc[G][1][2] += WV.y*a4.z; acc[G][1][3] += WV.y*a4.w; \
            acc[G][2][0] += WV.z*a4.x; acc[G][2][1] += WV.z*a4.y; acc[G][2][2] += WV.z*a4.z; acc[G][2][3] += WV.z*a4.w; \
            acc[G][3][0] += WV.w*a4.x; acc[G][3][1] += WV.w*a4.y; acc[G][3][2] += WV.w*a4.z; acc[G][3][3] += WV.w*a4.w; }
            MM(0, wr) MM(1, wu) MM(2, wm)
#undef MM
        }
        __syncthreads();   // guard: next tile's staging overwrites Ws/As
    }

    // epilogue: GRU gates for this thread's 4 channels x 4 pixels
    const float* i2h_t = g_i2h + (size_t)t * BB * C3 * HW;
    int np = n0 + tx * 4;

#pragma unroll
    for (int i = 0; i < 4; i++) {
        int c = ty * 4 + i;
        size_t base = ((size_t)b * C3 + c) * HW + np;
        float4 ir = *(const float4*)&i2h_t[base];
        float4 iu = *(const float4*)&i2h_t[base + (size_t)NF * HW];
        float4 im = *(const float4*)&i2h_t[base + (size_t)2 * NF * HW];
        float4 hp4 = *(const float4*)&hp[((size_t)b * NF + c) * HW + np];
        float br = bias[c], bu = bias[c + NF], bm = bias[c + 2 * NF];

        float4 outv;
#define GATE1(X, J) { \
        float r = fsigmoid(ir.X + acc[0][i][J] + br); \
        float u = fsigmoid(iu.X + acc[1][i][J] + bu); \
        float m = ftanh(im.X + r * (acc[2][i][J] + bm)); \
        outv.X = u * hp4.X + (1.f - u) * m; }
        GATE1(x, 0) GATE1(y, 1) GATE1(z, 2) GATE1(w, 3)
#undef GATE1

        *(float4*)&hn[((size_t)b * NF + c) * HW + np] = outv;
    }
}

// ==================== gates for t=0 only (h_prev = 0, h2h = bias) ====================
__global__ void gates_first_kernel(float* __restrict__ hn, const float* __restrict__ ret_b)
{
    int idx = blockIdx.x * blockDim.x + threadIdx.x;
    const int total4 = BB * NF * HW / 4;
    if (idx >= total4) return;

    int e = idx * 4;
    int pix = e % HW;
    int rest = e / HW;
    int c = rest % NF;
    int b = rest / NF;

    const float* i2h_t = g_i2h;   // t = 0
    size_t base = ((size_t)b * C3 + c) * HW + pix;
    float4 ir = *(const float4*)&i2h_t[base];
    float4 iu = *(const float4*)&i2h_t[base + (size_t)NF * HW];
    float4 im = *(const float4*)&i2h_t[base + (size_t)2 * NF * HW];

    float br = ret_b[c], bu = ret_b[c + NF], bm = ret_b[c + 2 * NF];

    float4 outv;
#define GATE1(X) { \
        float r = fsigmoid(ir.X + br); \
        float u = fsigmoid(iu.X + bu); \
        float m = ftanh(im.X + r * bm); \
        outv.X = (1.f - u) * m; }
    GATE1(x) GATE1(y) GATE1(z) GATE1(w)
#undef GATE1

    *(float4*)&hn[((size_t)b * NF + c) * HW + pix] = outv;
}

// -------------------- launcher --------------------
extern "C" void kernel_launch(void* const* d_in, const int* in_sizes, int n_in,
                              void* d_out, int out_size)
{
    const float* inputs  = (const float*)d_in[0];
    const float* i2h_w   = (const float*)d_in[1];
    const float* i2h_b   = (const float*)d_in[2];
    const float* i2f_w   = (const float*)d_in[3];
    const float* i2f_b   = (const float*)d_in[4];
    const float* h2f_w   = (const float*)d_in[5];
    const float* h2f_b   = (const float*)d_in[6];
    const float* flows_w = (const float*)d_in[7];
    const float* flows_b = (const float*)d_in[8];
    const float* ret_w   = (const float*)d_in[9];
    const float* ret_b   = (const float*)d_in[10];
    float* out = (float*)d_out;

    const int hstride = BB * NF * HW;
    const dim3 thr16(16, 16);

    conv3_kernel<<<dim3(9, C3 / 16, SEQ * BB), thr16>>>(inputs, i2h_w, i2h_b);

    for (int t = 0; t < SEQ; t++) {
        const float* x_t   = inputs + (size_t)t * BB * CIN * HW;
        const float* hprev = (t == 0) ? nullptr : out + (size_t)(t - 1) * hstride;
        float* hnew        = out + (size_t)t * hstride;
        int first = (t == 0) ? 1 : 0;

        conv5_f_kernel<<<dim3(9, CF / 8, BB), thr16>>>(x_t, hprev, i2f_w, h2f_w,
                                                       i2f_b, h2f_b, first);

        if (first) {
            gates_first_kernel<<<(hstride / 4 + 255) / 256, 256>>>(hnew, ret_b);
        } else {
            conv5_flows_kernel<<<dim3(9, 2, BB), thr16>>>(flows_w, flows_b);
            warp_gemm_gates_kernel<<<dim3(HW / 64, BB), 256>>>(ret_w, ret_b, t, hprev, hnew);
        }
    }

    if (out_size >= (SEQ + 1) * hstride) {
        copy_kernel<<<(hstride + 255) / 256, 256>>>(out + (size_t)(SEQ - 1) * hstride,
                                                    out + (size_t)SEQ * hstride, hstride);
    }
}

// round 17
// speedup vs baseline: 1.2002x; 1.0576x over previous
#include <cuda_runtime.h>
#include <cuda_bf16.h>
#include <math.h>

// Problem constants (fixed shapes)
#define SEQ   8
#define BB    8
#define CIN   16
#define HH    96
#define WW    96
#define HW    (HH*WW)      // 9216
#define NF    64
#define LL    5
#define C3    (3*NF)       // 192
#define CF    32           // f channels
#define CFL   (2*LL)       // 10 flow channels
#define KW    (LL*NF)      // 320 warped channels

// -------------------- scratch (device globals; no allocation) --------------------
__device__ float g_i2h  [(size_t)SEQ * BB * C3 * HW];
__device__ float g_f    [(size_t)BB * CF  * HW];
__device__ float g_flows[(size_t)BB * CFL * HW];

// fast transcendentals (accuracy budget is 1e-3; these are ~1e-7 level here)
__device__ __forceinline__ float fsigmoid(float x) {
    return 1.f / (1.f + __expf(-x));
}
__device__ __forceinline__ float ftanh(float x) {
    float e = __expf(2.f * x);
    return (e - 1.f) / (e + 1.f);
}

// -------------------- utility --------------------
__global__ void copy_kernel(const float* __restrict__ src, float* __restrict__ dst, int n) {
    int i = blockIdx.x * blockDim.x + threadIdx.x;
    if (i < n) dst[i] = src[i];
}

// ==================== conv3: i2h for ALL timesteps ====================
// 16 oc/block, 2x2 px/thread, 32x32 tile, double-buffered staging.
// grid (9, 12, SEQ*BB), block (16,16)
__global__ void __launch_bounds__(256, 2)
conv3_kernel(const float* __restrict__ x, const float* __restrict__ w,
             const float* __restrict__ bias)
{
    __shared__ __align__(16) float sm[2][34 * 34];
    __shared__ __align__(16) float sw[CIN * 16 * 12];   // [ic][o][12], pad 9->12

    int sb  = blockIdx.z;
    int ocg = blockIdx.y;
    int tileY = (blockIdx.x / 3) * 32;
    int tileX = (blockIdx.x % 3) * 32;
    int tid = threadIdx.y * 16 + threadIdx.x;

    for (int i = tid; i < CIN * 16 * 12; i += 256) {
        int ic = i / 192, rem = i % 192;
        int o = rem / 12, k = rem % 12;
        sw[i] = (k < 9) ? w[((ocg * 16 + o) * CIN + ic) * 9 + k] : 0.f;
    }

    const float* xb = x + (size_t)sb * CIN * HW;

    float rbuf[5];
#define C3_LD(IC) { \
        const float* src = xb + (size_t)(IC) * HW; \
        _Pragma("unroll") \
        for (int k = 0; k < 5; k++) { \
            int i = tid + k * 256; float v = 0.f; \
            if (i < 34 * 34) { \
                int r = i / 34, c = i % 34; \
                int gy = tileY + r - 1, gx = tileX + c - 1; \
                if ((unsigned)gy < (unsigned)HH && (unsigned)gx < (unsigned)WW) \
                    v = src[gy * WW + gx]; \
            } \
            rbuf[k] = v; \
        } }
#define C3_ST(BUF) { \
        _Pragma("unroll") \
        for (int k = 0; k < 5; k++) { \
            int i = tid + k * 256; \
            if (i < 34 * 34) sm[BUF][i] = rbuf[k]; \
        } }

    float acc[16][4];
#pragma unroll
    for (int o = 0; o < 16; o++)
#pragma unroll
        for (int p = 0; p < 4; p++) acc[o][p] = 0.f;

    C3_LD(0);
    int buf = 0;
    for (int ic = 0; ic < CIN; ic++) {
        C3_ST(buf);
        __syncthreads();
        if (ic + 1 < CIN) C3_LD(ic + 1);

        int ry = threadIdx.y * 2, rx = threadIdx.x * 2;
        float win[4][4];
#pragma unroll
        for (int i = 0; i < 4; i++) {
            float2 a = *(const float2*)&sm[buf][(ry + i) * 34 + rx];
            float2 bq = *(const float2*)&sm[buf][(ry + i) * 34 + rx + 2];
            win[i][0] = a.x; win[i][1] = a.y; win[i][2] = bq.x; win[i][3] = bq.y;
        }

#pragma unroll
        for (int o = 0; o < 16; o++) {
            float wv[12];
#pragma unroll
            for (int q = 0; q < 3; q++)
                *(float4*)&wv[q * 4] = *(const float4*)&sw[(ic * 16 + o) * 12 + q * 4];
#pragma unroll
            for (int py = 0; py < 2; py++)
#pragma unroll
                for (int px = 0; px < 2; px++) {
                    acc[o][py*2+px] +=
                        win[py  ][px]*wv[0] + win[py  ][px+1]*wv[1] + win[py  ][px+2]*wv[2]
                      + win[py+1][px]*wv[3] + win[py+1][px+1]*wv[4] + win[py+1][px+2]*wv[5]
                      + win[py+2][px]*wv[6] + win[py+2][px+1]*wv[7] + win[py+2][px+2]*wv[8];
                }
        }
        buf ^= 1;
    }
#undef C3_LD
#undef C3_ST

    int oy = tileY + threadIdx.y * 2, ox = tileX + threadIdx.x * 2;
#pragma unroll
    for (int o = 0; o < 16; o++) {
        float bv = bias[ocg * 16 + o];
        float* yp = g_i2h + ((size_t)sb * C3 + ocg * 16 + o) * HW;
        yp[oy * WW + ox]           = acc[o][0] + bv;
        yp[oy * WW + ox + 1]       = acc[o][1] + bv;
        yp[(oy + 1) * WW + ox]     = acc[o][2] + bv;
        yp[(oy + 1) * WW + ox + 1] = acc[o][3] + bv;
    }
}

// ==================== fused f conv: tanh(conv5(x) + conv5(h_prev)) ====================
// 8 oc/block, 2x2 px/thread, double-buffered; window LDS.64, weights padded 25->28.
// grid (9, 4, BB), block (16,16). Only launched for t>=1 (t=0's f is never consumed).
__global__ void __launch_bounds__(256, 2)
conv5_f_kernel(const float* __restrict__ x, const float* __restrict__ hp,
               const float* __restrict__ i2f_w, const float* __restrict__ h2f_w,
               const float* __restrict__ i2f_b, const float* __restrict__ h2f_b)
{
    __shared__ __align__(16) float sm[2][36 * 36];
    __shared__ __align__(16) float sw[2][8 * 28];

    int b   = blockIdx.z;
    int ocg = blockIdx.y;
    int tileY = (blockIdx.x / 3) * 32;
    int tileX = (blockIdx.x % 3) * 32;
    int tid = threadIdx.y * 16 + threadIdx.x;

    float acc[8][4];
#pragma unroll
    for (int o = 0; o < 8; o++)
#pragma unroll
        for (int p = 0; p < 4; p++) acc[o][p] = 0.f;

    const int ctot = CIN + NF;

    float rbuf[6], wreg = 0.f;
#define F_LD(IC) { \
        const float* src; const float* wsrc; int cnum, icl; \
        if ((IC) < CIN) { src = x + ((size_t)b * CIN + (IC)) * HW; wsrc = i2f_w; cnum = CIN; icl = (IC); } \
        else { src = hp + ((size_t)b * NF + ((IC) - CIN)) * HW; wsrc = h2f_w; cnum = NF; icl = (IC) - CIN; } \
        _Pragma("unroll") \
        for (int k = 0; k < 6; k++) { \
            int i = tid + k * 256; float v = 0.f; \
            if (i < 36 * 36) { \
                int r = i / 36, c = i % 36; \
                int gy = tileY + r - 2, gx = tileX + c - 2; \
                if ((unsigned)gy < (unsigned)HH && (unsigned)gx < (unsigned)WW) \
                    v = src[gy * WW + gx]; \
            } \
            rbuf[k] = v; \
        } \
        if (tid < 224) { \
            int o = tid / 28, kk = tid % 28; \
            wreg = (kk < 25) ? wsrc[((size_t)(ocg * 8 + o) * cnum + icl) * 25 + kk] : 0.f; \
        } }
#define F_ST(BUF) { \
        _Pragma("unroll") \
        for (int k = 0; k < 6; k++) { \
            int i = tid + k * 256; \
            if (i < 36 * 36) sm[BUF][i] = rbuf[k]; \
        } \
        if (tid < 224) sw[BUF][tid] = wreg; }

    F_LD(0);
    int buf = 0;
    for (int ic = 0; ic < ctot; ic++) {
        F_ST(buf);
        __syncthreads();
        if (ic + 1 < ctot) F_LD(ic + 1);

        int ry = threadIdx.y * 2, rx = threadIdx.x * 2;
        float win[6][6];
#pragma unroll
        for (int i = 0; i < 6; i++) {
            float2 a = *(const float2*)&sm[buf][(ry + i) * 36 + rx];
            float2 bq = *(const float2*)&sm[buf][(ry + i) * 36 + rx + 2];
            float2 cq = *(const float2*)&sm[buf][(ry + i) * 36 + rx + 4];
            win[i][0] = a.x;  win[i][1] = a.y;
            win[i][2] = bq.x; win[i][3] = bq.y;
            win[i][4] = cq.x; win[i][5] = cq.y;
        }

#pragma unroll
        for (int o = 0; o < 8; o++) {
            float wv[28];
#pragma unroll
            for (int q = 0; q < 7; q++)
                *(float4*)&wv[q * 4] = *(const float4*)&sw[buf][o * 28 + q * 4];
#pragma unroll
            for (int ky = 0; ky < 5; ky++)
#pragma unroll
                for (int kx = 0; kx < 5; kx++) {
                    float wvv = wv[ky * 5 + kx];
                    acc[o][0] += win[ky  ][kx  ] * wvv;
                    acc[o][1] += win[ky  ][kx+1] * wvv;
                    acc[o][2] += win[ky+1][kx  ] * wvv;
                    acc[o][3] += win[ky+1][kx+1] * wvv;
                }
        }
        buf ^= 1;
    }
#undef F_LD
#undef F_ST

    int oy = tileY + threadIdx.y * 2, ox = tileX + threadIdx.x * 2;
#pragma unroll
    for (int o = 0; o < 8; o++) {
        int oc = ocg * 8 + o;
        float bv = i2f_b[oc] + h2f_b[oc];
        float* yp = g_f + ((size_t)b * CF + oc) * HW;
        yp[oy * WW + ox]           = ftanh(acc[o][0] + bv);
        yp[oy * WW + ox + 1]       = ftanh(acc[o][1] + bv);
        yp[(oy + 1) * WW + ox]     = ftanh(acc[o][2] + bv);
        yp[(oy + 1) * WW + ox + 1] = ftanh(acc[o][3] + bv);
    }
}

// ==================== flows conv: conv5(g_f) -> g_flows ====================
// 2 oc-groups of 5 for full-chip parallelism. grid (9, 2, BB), block (16,16)
#define FL_OCG 5
__global__ void __launch_bounds__(256, 2)
conv5_flows_kernel(const float* __restrict__ flows_w, const float* __restrict__ flows_b)
{
    __shared__ __align__(16) float sm[2][36 * 36];
    __shared__ __align__(16) float sw[FL_OCG * CF * 28];

    int b   = blockIdx.z;
    int ocg = blockIdx.y;          // 0 or 1
    int oc0 = ocg * FL_OCG;
    int tileY = (blockIdx.x / 3) * 32;
    int tileX = (blockIdx.x % 3) * 32;
    int tid = threadIdx.y * 16 + threadIdx.x;

    for (int i = tid; i < FL_OCG * CF * 28; i += 256) {
        int k = i % 28;
        int oc_ic = i / 28;
        int o = oc_ic / CF, ic = oc_ic % CF;
        sw[i] = (k < 25) ? flows_w[((oc0 + o) * CF + ic) * 25 + k] : 0.f;
    }

    float acc[FL_OCG][4];
#pragma unroll
    for (int o = 0; o < FL_OCG; o++)
#pragma unroll
        for (int p = 0; p < 4; p++) acc[o][p] = 0.f;

    float rbuf[6];
#define FL_LD(IC) { \
        const float* src = g_f + ((size_t)b * CF + (IC)) * HW; \
        _Pragma("unroll") \
        for (int k = 0; k < 6; k++) { \
            int i = tid + k * 256; float v = 0.f; \
            if (i < 36 * 36) { \
                int r = i / 36, c = i % 36; \
                int gy = tileY + r - 2, gx = tileX + c - 2; \
                if ((unsigned)gy < (unsigned)HH && (unsigned)gx < (unsigned)WW) \
                    v = src[gy * WW + gx]; \
            } \
            rbuf[k] = v; \
        } }
#define FL_ST(BUF) { \
        _Pragma("unroll") \
        for (int k = 0; k < 6; k++) { \
            int i = tid + k * 256; \
            if (i < 36 * 36) sm[BUF][i] = rbuf[k]; \
        } }

    FL_LD(0);
    int buf = 0;
    for (int ic = 0; ic < CF; ic++) {
        FL_ST(buf);
        __syncthreads();
        if (ic + 1 < CF) FL_LD(ic + 1);

        int ry = threadIdx.y * 2, rx = threadIdx.x * 2;
        float win[6][6];
#pragma unroll
        for (int i = 0; i < 6; i++) {
            float2 a = *(const float2*)&sm[buf][(ry + i) * 36 + rx];
            float2 bq = *(const float2*)&sm[buf][(ry + i) * 36 + rx + 2];
            float2 cq = *(const float2*)&sm[buf][(ry + i) * 36 + rx + 4];
            win[i][0] = a.x;  win[i][1] = a.y;
            win[i][2] = bq.x; win[i][3] = bq.y;
            win[i][4] = cq.x; win[i][5] = cq.y;
        }

#pragma unroll
        for (int o = 0; o < FL_OCG; o++) {
            float wv[28];
#pragma unroll
            for (int q = 0; q < 7; q++)
                *(float4*)&wv[q * 4] = *(const float4*)&sw[(o * CF + ic) * 28 + q * 4];
#pragma unroll
            for (int ky = 0; ky < 5; ky++)
#pragma unroll
                for (int kx = 0; kx < 5; kx++) {
                    float wvv = wv[ky * 5 + kx];
                    acc[o][0] += win[ky  ][kx  ] * wvv;
                    acc[o][1] += win[ky  ][kx+1] * wvv;
                    acc[o][2] += win[ky+1][kx  ] * wvv;
                    acc[o][3] += win[ky+1][kx+1] * wvv;
                }
        }
        buf ^= 1;
    }
#undef FL_LD
#undef FL_ST

    int oy = tileY + threadIdx.y * 2, ox = tileX + threadIdx.x * 2;
#pragma unroll
    for (int o = 0; o < FL_OCG; o++) {
        float bv = flows_b[oc0 + o];
        float* yp = g_flows + ((size_t)b * CFL + oc0 + o) * HW;
        yp[oy * WW + ox]           = acc[o][0] + bv;
        yp[oy * WW + ox + 1]       = acc[o][1] + bv;
        yp[(oy + 1) * WW + ox]     = acc[o][2] + bv;
        yp[(oy + 1) * WW + ox + 1] = acc[o][3] + bv;
    }
}

// ==================== fused warp + GEMM + gates (BK=32, f32x2 FMA) ====================
// MMA loop uses packed fma.rn.f32x2: accumulators paired along the channel dim so
// weight pairs come pre-packed from contiguous smem (LDS.128 -> 2 pairs); only the
// broadcast A operand needs mov.b64 {a,a} packs (4/kk). Per-lane math is fused fp32
// FMA -> bitwise-identical results. grid (144, BB), block 256.
__global__ void __launch_bounds__(256, 2)
warp_gemm_gates_kernel(const float* __restrict__ Wm, const float* __restrict__ bias,
                       int t, const float* __restrict__ hp, float* __restrict__ hn)
{
    const int K = KW, N = HW;
    __shared__ __align__(16) float Ws[32][196];      // 24.5 KB (padded 192->196)
    __shared__ __align__(16) float As[32][68];       //  8.5 KB (padded 64->68)
    __shared__ __align__(16) int4   s_off[LL][64];   //  5 KB
    __shared__ __align__(16) float4 s_wt [LL][64];   //  5 KB

    int b  = blockIdx.y;
    int n0 = blockIdx.x * 64;
    int tid = threadIdx.x;
    int tx = tid % 16;        // pixel group: 4 px
    int ty = tid / 16;        // channel group: c0 = ty*4

    // ---- precompute bilinear taps for this block's 64 pixels x 5 levels ----
    for (int i = tid; i < LL * 64; i += 256) {
        int l = i / 64, p = i % 64;
        int pix = n0 + p;
        int gx = pix % WW;
        int gy = pix / WW;

        const float* fl = g_flows + ((size_t)b * CFL + 2 * l) * HW;
        float fx = fl[pix];
        float fy = fl[HW + pix];

        float vx = (float)gx - fx;
        float vy = (float)gy - fy;
        float gxn = 2.f * vx / (float)(WW - 1) - 1.f;
        float gyn = 2.f * vy / (float)(HH - 1) - 1.f;
        float sx = ((gxn + 1.f) * (float)WW - 1.f) * 0.5f;
        float sy = ((gyn + 1.f) * (float)HH - 1.f) * 0.5f;

        float x0f = floorf(sx), y0f = floorf(sy);
        int x0 = (int)x0f, y0 = (int)y0f;
        int x1 = x0 + 1, y1 = y0 + 1;
        float wx1 = sx - x0f, wx0 = 1.f - wx1;
        float wy1 = sy - y0f, wy0 = 1.f - wy1;

        bool vx0 = (x0 >= 0) && (x0 < WW);
        bool vx1 = (x1 >= 0) && (x1 < WW);
        bool vy0 = (y0 >= 0) && (y0 < HH);
        bool vy1 = (y1 >= 0) && (y1 < HH);

        int xc0 = min(max(x0, 0), WW - 1);
        int xc1 = min(max(x1, 0), WW - 1);
        int yc0 = min(max(y0, 0), HH - 1);
        int yc1 = min(max(y1, 0), HH - 1);

        float4 wt;
        wt.x = (vy0 && vx0) ? wy0 * wx0 : 0.f;
        wt.y = (vy0 && vx1) ? wy0 * wx1 : 0.f;
        wt.z = (vy1 && vx0) ? wy1 * wx0 : 0.f;
        wt.w = (vy1 && vx1) ? wy1 * wx1 : 0.f;

        int4 off;
        off.x = yc0 * WW + xc0;
        off.y = yc0 * WW + xc1;
        off.z = yc1 * WW + xc0;
        off.w = yc1 * WW + xc1;

        s_off[l][p] = off;
        s_wt[l][p]  = wt;
    }
    __syncthreads();

    const float* hpb = hp + (size_t)b * NF * HW;

    // packed accumulators: acc2[g][cp][px] holds channels (ty*4+2cp, ty*4+2cp+1)
    unsigned long long acc2[3][2][4];
#pragma unroll
    for (int g = 0; g < 3; g++)
#pragma unroll
        for (int i = 0; i < 2; i++)
#pragma unroll
            for (int j = 0; j < 4; j++) acc2[g][i][j] = 0ULL;

    int arow = tid / 16;      // 0..15
    int acol = (tid % 16) * 4;

    for (int k0 = 0; k0 < K; k0 += 32) {
        // ---- stage W directly into smem (24 elems/thread; 32x192 total) ----
#pragma unroll
        for (int r = 0; r < 24; r++) {
            int i = tid + r * 256;
            int m = i >> 5, kk = i & 31;
            Ws[kk][m] = Wm[(size_t)m * K + k0 + kk];
        }
        // ---- stage gathered A directly into smem (2 rows x 4 px per thread) ----
        {
            int l = k0 / 64;
#pragma unroll
            for (int h = 0; h < 2; h++) {
                int r2 = arow + h * 16;
                int c = (k0 & 63) + r2;
                const float* hc = hpb + (size_t)c * HW;
#pragma unroll
                for (int j = 0; j < 4; j++) {
                    int p = acol + j;
                    int4   o4 = s_off[l][p];
                    float4 w4 = s_wt[l][p];
                    As[r2][p] = w4.x * __ldg(hc + o4.x) + w4.y * __ldg(hc + o4.y)
                              + w4.z * __ldg(hc + o4.z) + w4.w * __ldg(hc + o4.w);
                }
            }
        }
        __syncthreads();

#pragma unroll
        for (int kk = 0; kk < 32; kk++) {
            float4 a4 = *(const float4*)&As[kk][tx * 4];
            ulonglong2 wr = *(const ulonglong2*)&Ws[kk][ty * 4];
            ulonglong2 wu = *(const ulonglong2*)&Ws[kk][ty * 4 + 64];
            ulonglong2 wm = *(const ulonglong2*)&Ws[kk][ty * 4 + 128];
            unsigned long long ap[4];
            asm("mov.b64 %0, {%1, %1};" : "=l"(ap[0]) : "r"(__float_as_uint(a4.x)));
            asm("mov.b64 %0, {%1, %1};" : "=l"(ap[1]) : "r"(__float_as_uint(a4.y)));
            asm("mov.b64 %0, {%1, %1};" : "=l"(ap[2]) : "r"(__float_as_uint(a4.z)));
            asm("mov.b64 %0, {%1, %1};" : "=l"(ap[3]) : "r"(__float_as_uint(a4.w)));
#define FMM(G, WP) { \
            _Pragma("unroll") \
            for (int j = 0; j < 4; j++) { \
                asm("fma.rn.f32x2 %0, %1, %2, %0;" : "+l"(acc2[G][0][j]) : "l"(WP.x), "l"(ap[j])); \
                asm("fma.rn.f32x2 %0, %1, %2, %0;" : "+l"(acc2[G][1][j]) : "l"(WP.y), "l"(ap[j])); \
            } }
            FMM(0, wr) FMM(1, wu) FMM(2, wm)
#undef FMM
        }
        __syncthreads();   // guard: next tile's staging overwrites Ws/As
    }

    // unpack packed accumulators: lane0 (low 32b) = channel 2*cp, lane1 = 2*cp+1
    float acc[3][4][4];
#pragma unroll
    for (int g = 0; g < 3; g++)
#pragma unroll
        for (int cp = 0; cp < 2; cp++)
#pragma unroll
            for (int j = 0; j < 4; j++) {
                unsigned lo, hi;
                asm("mov.b64 {%0, %1}, %2;" : "=r"(lo), "=r"(hi) : "l"(acc2[g][cp][j]));
                acc[g][cp * 2][j]     = __uint_as_float(lo);
                acc[g][cp * 2 + 1][j] = __uint_as_float(hi);
            }

    // epilogue: GRU gates for this thread's 4 channels x 4 pixels
    const float* i2h_t = g_i2h + (size_t)t * BB * C3 * HW;
    int np = n0 + tx * 4;

#pragma unroll
    for (int i = 0; i < 4; i++) {
        int c = ty * 4 + i;
        size_t base = ((size_t)b * C3 + c) * HW + np;
        float4 ir = *(const float4*)&i2h_t[base];
        float4 iu = *(const float4*)&i2h_t[base + (size_t)NF * HW];
        float4 im = *(const float4*)&i2h_t[base + (size_t)2 * NF * HW];
        float4 hp4 = *(const float4*)&hp[((size_t)b * NF + c) * HW + np];
        float br = bias[c], bu = bias[c + NF], bm = bias[c + 2 * NF];

        float4 outv;
#define GATE1(X, J) { \
        float r = fsigmoid(ir.X + acc[0][i][J] + br); \
        float u = fsigmoid(iu.X + acc[1][i][J] + bu); \
        float m = ftanh(im.X + r * (acc[2][i][J] + bm)); \
        outv.X = u * hp4.X + (1.f - u) * m; }
        GATE1(x, 0) GATE1(y, 1) GATE1(z, 2) GATE1(w, 3)
#undef GATE1

        *(float4*)&hn[((size_t)b * NF + c) * HW + np] = outv;
    }
}

// ==================== gates for t=0 only (h_prev = 0, h2h = bias) ====================
__global__ void gates_first_kernel(float* __restrict__ hn, const float* __restrict__ ret_b)
{
    int idx = blockIdx.x * blockDim.x + threadIdx.x;
    const int total4 = BB * NF * HW / 4;
    if (idx >= total4) return;

    int e = idx * 4;
    int pix = e % HW;
    int rest = e / HW;
    int c = rest % NF;
    int b = rest / NF;

    const float* i2h_t = g_i2h;   // t = 0
    size_t base = ((size_t)b * C3 + c) * HW + pix;
    float4 ir = *(const float4*)&i2h_t[base];
    float4 iu = *(const float4*)&i2h_t[base + (size_t)NF * HW];
    float4 im = *(const float4*)&i2h_t[base + (size_t)2 * NF * HW];

    float br = ret_b[c], bu = ret_b[c + NF], bm = ret_b[c + 2 * NF];

    float4 outv;
#define GATE1(X) { \
        float r = fsigmoid(ir.X + br); \
        float u = fsigmoid(iu.X + bu); \
        float m = ftanh(im.X + r * bm); \
        outv.X = (1.f - u) * m; }
    GATE1(x) GATE1(y) GATE1(z) GATE1(w)
#undef GATE1

    *(float4*)&hn[((size_t)b * NF + c) * HW + pix] = outv;
}

// -------------------- launcher --------------------
extern "C" void kernel_launch(void* const* d_in, const int* in_sizes, int n_in,
                              void* d_out, int out_size)
{
    const float* inputs  = (const float*)d_in[0];
    const float* i2h_w   = (const float*)d_in[1];
    const float* i2h_b   = (const float*)d_in[2];
    const float* i2f_w   = (const float*)d_in[3];
    const float* i2f_b   = (const float*)d_in[4];
    const float* h2f_w   = (const float*)d_in[5];
    const float* h2f_b   = (const float*)d_in[6];
    const float* flows_w = (const float*)d_in[7];
    const float* flows_b = (const float*)d_in[8];
    const float* ret_w   = (const float*)d_in[9];
    const float* ret_b   = (const float*)d_in[10];
    float* out = (float*)d_out;

    const int hstride = BB * NF * HW;
    const dim3 thr16(16, 16);

    conv3_kernel<<<dim3(9, C3 / 16, SEQ * BB), thr16>>>(inputs, i2h_w, i2h_b);

    for (int t = 0; t < SEQ; t++) {
        const float* x_t   = inputs + (size_t)t * BB * CIN * HW;
        const float* hprev = (t == 0) ? nullptr : out + (size_t)(t - 1) * hstride;
        float* hnew        = out + (size_t)t * hstride;

        if (t == 0) {
            // f(t0) is never consumed (warp of h0=0 is zero regardless) -> skip conv5_f
            gates_first_kernel<<<(hstride / 4 + 255) / 256, 256>>>(hnew, ret_b);
        } else {
            conv5_f_kernel<<<dim3(9, CF / 8, BB), thr16>>>(x_t, hprev, i2f_w, h2f_w,
                                                           i2f_b, h2f_b);
            conv5_flows_kernel<<<dim3(9, 2, BB), thr16>>>(flows_w, flows_b);
            warp_gemm_gates_kernel<<<dim3(HW / 64, BB), 256>>>(ret_w, ret_b, t, hprev, hnew);
        }
    }

    if (out_size >= (SEQ + 1) * hstride) {
        copy_kernel<<<(hstride + 255) / 256, 256>>>(out + (size_t)(SEQ - 1) * hstride,
                                                    out + (size_t)SEQ * hstride, hstride);
    }
}